// round 4
// baseline (speedup 1.0000x reference)
#include <cuda_runtime.h>
#include <math.h>

#define B_  4
#define H_  8
#define D_  512
#define HD_ 64
#define NQ_ 512
#define NK_ 4096

// exp(s/8) == exp2(s * 0.125 * log2(e))
#define EXPC 0.18033688011112042f

// ---------------- scratch (no-alloc rule) ----------------
__device__ float g_Q[(size_t)B_ * H_ * NQ_ * HD_];    // [B,H,NQ,HD] tf32-rounded
__device__ float g_K[(size_t)B_ * H_ * NK_ * HD_];    // [B,H,NK,HD] tf32-rounded
__device__ float g_V[(size_t)B_ * H_ * NK_ * HD_];    // [B,H,NK,HD] tf32-rounded
__device__ float g_ctx[(size_t)B_ * NQ_ * D_];        // [B,NQ,D]

// ---------------- helpers ----------------
__device__ __forceinline__ unsigned f2tf32(float x) {
    unsigned r;
    asm("cvt.rna.tf32.f32 %0, %1;" : "=r"(r) : "f"(x));
    return r;
}

__device__ __forceinline__ void mma_tf32(float* d, const unsigned* a,
                                         const unsigned* b) {
    asm volatile(
        "mma.sync.aligned.m16n8k8.row.col.f32.tf32.tf32.f32 "
        "{%0,%1,%2,%3}, {%4,%5,%6,%7}, {%8,%9}, {%0,%1,%2,%3};"
        : "+f"(d[0]), "+f"(d[1]), "+f"(d[2]), "+f"(d[3])
        : "r"(a[0]), "r"(a[1]), "r"(a[2]), "r"(a[3]),
          "r"(b[0]), "r"(b[1]));
}

__device__ __forceinline__ void cpa16(unsigned dst, const void* src) {
    asm volatile("cp.async.cg.shared.global [%0], [%1], 16;\n"
                 :: "r"(dst), "l"(src));
}
__device__ __forceinline__ void cpa_commit() {
    asm volatile("cp.async.commit_group;\n" ::: "memory");
}
template <int N>
__device__ __forceinline__ void cpa_wait() {
    asm volatile("cp.async.wait_group %0;\n" :: "n"(N) : "memory");
}

// ---------------------------------------------------------------------------
// TF32 projection GEMM: Y = X @ W^T + bias.
// SPLIT=true additionally rounds outputs to tf32 (bit-exact tf32-in-fp32) so
// the attention kernel can cp.async them with no conversion.
// ---------------------------------------------------------------------------
template <bool SPLIT>
__global__ __launch_bounds__(256, 2) void proj_tc(
    const float* __restrict__ X, const float* __restrict__ W,
    const float* __restrict__ bias, float* __restrict__ Y, int N_seq)
{
    __shared__ unsigned Xs[128 * 36];
    __shared__ unsigned Ws[128 * 36];

    const int tid  = threadIdx.x;
    const int lane = tid & 31;
    const int w    = tid >> 5;
    const int wm   = w >> 2;
    const int wn   = w & 3;
    const int g    = lane >> 2;
    const int t    = lane & 3;
    const int bm   = blockIdx.x * 128;
    const int bn   = blockIdx.y * 128;

    float acc[4][4][4];
#pragma unroll
    for (int mi = 0; mi < 4; mi++)
#pragma unroll
        for (int nj = 0; nj < 4; nj++)
#pragma unroll
            for (int rr = 0; rr < 4; rr++) acc[mi][nj][rr] = 0.0f;

    for (int k0 = 0; k0 < D_; k0 += 32) {
        __syncthreads();
#pragma unroll
        for (int it = 0; it < 4; it++) {
            int i = it * 256 + tid;
            int r = i >> 3, c = (i & 7) * 4;
            float4 vx = *reinterpret_cast<const float4*>(
                &X[(size_t)(bm + r) * D_ + k0 + c]);
            uint4 ux = make_uint4(f2tf32(vx.x), f2tf32(vx.y), f2tf32(vx.z), f2tf32(vx.w));
            *reinterpret_cast<uint4*>(&Xs[r * 36 + c]) = ux;
            float4 vw = *reinterpret_cast<const float4*>(
                &W[(size_t)(bn + r) * D_ + k0 + c]);
            uint4 uw = make_uint4(f2tf32(vw.x), f2tf32(vw.y), f2tf32(vw.z), f2tf32(vw.w));
            *reinterpret_cast<uint4*>(&Ws[r * 36 + c]) = uw;
        }
        __syncthreads();

#pragma unroll
        for (int k8 = 0; k8 < 4; k8++) {
            unsigned a[4][4], b[4][2];
            int kk = k8 * 8 + t;
#pragma unroll
            for (int mi = 0; mi < 4; mi++) {
                int r = wm * 64 + mi * 16 + g;
                a[mi][0] = Xs[r * 36 + kk];
                a[mi][1] = Xs[(r + 8) * 36 + kk];
                a[mi][2] = Xs[r * 36 + kk + 4];
                a[mi][3] = Xs[(r + 8) * 36 + kk + 4];
            }
#pragma unroll
            for (int nj = 0; nj < 4; nj++) {
                int n = wn * 32 + nj * 8 + g;
                b[nj][0] = Ws[n * 36 + kk];
                b[nj][1] = Ws[n * 36 + kk + 4];
            }
#pragma unroll
            for (int mi = 0; mi < 4; mi++)
#pragma unroll
                for (int nj = 0; nj < 4; nj++)
                    mma_tf32(acc[mi][nj], a[mi], b[nj]);
        }
    }

#pragma unroll
    for (int mi = 0; mi < 4; mi++) {
#pragma unroll
        for (int nj = 0; nj < 4; nj++) {
            int n = bn + wn * 32 + nj * 8 + t * 2;
            float b0 = bias[n], b1 = bias[n + 1];
#pragma unroll
            for (int rr = 0; rr < 2; rr++) {
                int m = bm + wm * 64 + mi * 16 + g + rr * 8;
                float v0 = acc[mi][nj][rr * 2] + b0;
                float v1 = acc[mi][nj][rr * 2 + 1] + b1;
                float2 v;
                if (SPLIT) {
                    v = make_float2(__uint_as_float(f2tf32(v0)),
                                    __uint_as_float(f2tf32(v1)));
                    int bb = m / N_seq;
                    int s  = m - bb * N_seq;
                    int h  = n >> 6;
                    int hd = n & 63;
                    *reinterpret_cast<float2*>(
                        &Y[((((size_t)bb * H_ + h) * N_seq + s) << 6) + hd]) = v;
                } else {
                    v = make_float2(v0, v1);
                    *reinterpret_cast<float2*>(&Y[(size_t)m * D_ + n]) = v;
                }
            }
        }
    }
}

// ---------------------------------------------------------------------------
// Single-pass TF32 fused attention, max-free softmax.
// CTA = (bh, qt): 64 q rows, ktile 64. 8 warps as 4m x 2n, warp tile 16 x 32.
// Q fragments live in registers. K/V double-buffered via cp.async.
// Per ktile: S-mma -> exp (unnormalized) -> STG A + STS P -> PV-mma.
// Epilogue: reduce row sums, scale ctx, and rescale own A rows in gmem.
// ---------------------------------------------------------------------------
#define STRK 68
#define STRV 72
#define STRP 68
#define KBUF 4352           // 64*68
#define VBUF 4608           // 64*72
#define OFV  8704           // 2*KBUF
#define OFP  17920          // OFV + 2*VBUF
#define OFRED 22272         // OFP + 4352
#define OFL  22400
#define ATT_SMEM_FLOATS 22464   // 89856 bytes

__global__ __launch_bounds__(256, 2) void attn_tc(
    const float* __restrict__ gQ, const float* __restrict__ gK,
    const float* __restrict__ gV, float* __restrict__ A_out,
    float* __restrict__ gctx)
{
    extern __shared__ float sm[];
    float* Kb   = sm;                // [2][64*STRK]
    float* Vb   = sm + OFV;          // [2][64*STRV]
    float* Ps   = sm + OFP;          // [64*STRP]  (also Q staging in prologue)
    float* red  = sm + OFRED;        // [128]
    float* linv = sm + OFL;          // [64]

    const int tid  = threadIdx.x;
    const int lane = tid & 31;
    const int w    = tid >> 5;
    const int g    = lane >> 2;
    const int t    = lane & 3;
    const int wm   = w >> 1;       // 0..3  (16 q rows)
    const int wn   = w & 1;        // 0..1  (32 cols)
    const int bh   = blockIdx.x >> 3;
    const int qt   = blockIdx.x & 7;

    const float* Qg = gQ + ((size_t)bh * NQ_ + qt * 64) * HD_;
    const float* Kg = gK + (size_t)bh * NK_ * HD_;
    const float* Vg = gV + (size_t)bh * NK_ * HD_;
    float* Ab = A_out + ((size_t)bh * NQ_ + qt * 64) * NK_;

    const int pr = tid >> 4;               // 0..15
    const int pc = (tid & 15) * 4;         // 0..60

    unsigned kb_u = (unsigned)__cvta_generic_to_shared(Kb);
    unsigned vb_u = (unsigned)__cvta_generic_to_shared(Vb);
    unsigned ps_u = (unsigned)__cvta_generic_to_shared(Ps);

    // prologue: Q -> Ps staging (group 0)
#pragma unroll
    for (int it = 0; it < 4; it++) {
        int r = it * 16 + pr;
        cpa16(ps_u + (r * STRP + pc) * 4, Qg + (size_t)r * HD_ + pc);
    }
    cpa_commit();
    // K0,V0 -> buf0 (group 1)
#pragma unroll
    for (int it = 0; it < 4; it++) {
        int r = it * 16 + pr;
        cpa16(kb_u + (r * STRK + pc) * 4, Kg + (size_t)r * HD_ + pc);
        cpa16(vb_u + (r * STRV + pc) * 4, Vg + (size_t)r * HD_ + pc);
    }
    cpa_commit();

    cpa_wait<1>();          // Q staged
    __syncthreads();

    // Q fragments -> registers (reused for all 64 ktiles)
    unsigned qa[8][4];
    const int r0 = wm * 16 + g;
#pragma unroll
    for (int k8 = 0; k8 < 8; k8++) {
        int kk = k8 * 8 + t;
        qa[k8][0] = __float_as_uint(Ps[r0 * STRP + kk]);
        qa[k8][1] = __float_as_uint(Ps[(r0 + 8) * STRP + kk]);
        qa[k8][2] = __float_as_uint(Ps[r0 * STRP + kk + 4]);
        qa[k8][3] = __float_as_uint(Ps[(r0 + 8) * STRP + kk + 4]);
    }

    float psum[2] = {0.0f, 0.0f};
    float ctx[4][4];
#pragma unroll
    for (int nj = 0; nj < 4; nj++)
#pragma unroll
        for (int rr = 0; rr < 4; rr++) ctx[nj][rr] = 0.0f;

    for (int kt = 0; kt < 64; kt++) {
        cpa_wait<0>();      // buf[kt&1] complete (all threads' copies)
        __syncthreads();    // visible CTA-wide; also: everyone done with buf[(kt+1)&1]

        if (kt < 63) {      // issue next tile into the other buffer (overlaps mma)
            const float* Kn = Kg + (size_t)(kt + 1) * 64 * HD_;
            const float* Vn = Vg + (size_t)(kt + 1) * 64 * HD_;
            unsigned kdst = kb_u + ((kt + 1) & 1) * KBUF * 4;
            unsigned vdst = vb_u + ((kt + 1) & 1) * VBUF * 4;
#pragma unroll
            for (int it = 0; it < 4; it++) {
                int r = it * 16 + pr;
                cpa16(kdst + (r * STRK + pc) * 4, Kn + (size_t)r * HD_ + pc);
                cpa16(vdst + (r * STRV + pc) * 4, Vn + (size_t)r * HD_ + pc);
            }
            cpa_commit();
        }

        const unsigned* Ks = (const unsigned*)(Kb + (kt & 1) * KBUF);
        const unsigned* Vs = (const unsigned*)(Vb + (kt & 1) * VBUF);

        // ---- S = Q K^T (warp 16 x 32) ----
        float s[4][4];
#pragma unroll
        for (int nj = 0; nj < 4; nj++)
#pragma unroll
            for (int rr = 0; rr < 4; rr++) s[nj][rr] = 0.0f;

#pragma unroll
        for (int k8 = 0; k8 < 8; k8++) {
            unsigned b[4][2];
            int kk = k8 * 8 + t;
#pragma unroll
            for (int nj = 0; nj < 4; nj++) {
                int n = wn * 32 + nj * 8 + g;
                b[nj][0] = Ks[n * STRK + kk];
                b[nj][1] = Ks[n * STRK + kk + 4];
            }
#pragma unroll
            for (int nj = 0; nj < 4; nj++)
                mma_tf32(s[nj], qa[k8], b[nj]);
        }

        // ---- exp (unnormalized), accumulate row sums, write A, stage P ----
#pragma unroll
        for (int rr = 0; rr < 2; rr++) {
            int row = r0 + rr * 8;
            float acc = 0.0f;
#pragma unroll
            for (int nj = 0; nj < 4; nj++) {
                float p0 = exp2f(s[nj][rr * 2] * EXPC);
                float p1 = exp2f(s[nj][rr * 2 + 1] * EXPC);
                acc += p0 + p1;
                int col = wn * 32 + nj * 8 + t * 2;
                *reinterpret_cast<float2*>(
                    &Ab[(size_t)row * NK_ + kt * 64 + col]) = make_float2(p0, p1);
                Ps[row * STRP + col]     = __uint_as_float(f2tf32(p0));
                Ps[row * STRP + col + 1] = __uint_as_float(f2tf32(p1));
            }
            psum[rr] += acc;
        }
        __syncthreads();    // P (and V) ready

        // ---- ctx += P V ----
        const unsigned* Pu = (const unsigned*)Ps;
#pragma unroll
        for (int k8 = 0; k8 < 8; k8++) {
            unsigned a[4], b[4][2];
            int kk = k8 * 8 + t;
            a[0] = Pu[r0 * STRP + kk];
            a[1] = Pu[(r0 + 8) * STRP + kk];
            a[2] = Pu[r0 * STRP + kk + 4];
            a[3] = Pu[(r0 + 8) * STRP + kk + 4];
#pragma unroll
            for (int nj = 0; nj < 4; nj++) {
                int n = wn * 32 + nj * 8 + g;
                b[nj][0] = Vs[kk * STRV + n];
                b[nj][1] = Vs[(kk + 4) * STRV + n];
            }
#pragma unroll
            for (int nj = 0; nj < 4; nj++)
                mma_tf32(ctx[nj], a, b[nj]);
        }
    }

    // ---- reduce row sums -> linv ----
#pragma unroll
    for (int rr = 0; rr < 2; rr++) {
        float v = psum[rr];
        v += __shfl_xor_sync(0xffffffffu, v, 1);
        v += __shfl_xor_sync(0xffffffffu, v, 2);
        if (t == 0) red[wn * 64 + r0 + rr * 8] = v;
    }
    __syncthreads();
    if (tid < 64) linv[tid] = 1.0f / (red[tid] + red[64 + tid]);
    __syncthreads();

    // ---- scale + write ctx ----
    const int b0 = bh >> 3;
    const int h  = bh & 7;
    float li[2];
    li[0] = linv[r0];
    li[1] = linv[r0 + 8];
#pragma unroll
    for (int nj = 0; nj < 4; nj++) {
        int hd = wn * 32 + nj * 8 + t * 2;
#pragma unroll
        for (int rr = 0; rr < 2; rr++) {
            int q = qt * 64 + r0 + rr * 8;
            float2 v = make_float2(ctx[nj][rr * 2] * li[rr],
                                   ctx[nj][rr * 2 + 1] * li[rr]);
            *reinterpret_cast<float2*>(
                &gctx[((size_t)b0 * NQ_ + q) * D_ + h * 64 + hd]) = v;
        }
    }

    // ---- normalize this CTA's A rows in place (overlaps other CTAs' work) ----
#pragma unroll 4
    for (int it = 0; it < 256; it++) {
        int i = it * 256 + tid;             // 65536 float4 total
        int r = i >> 10;
        int c = (i & 1023) * 4;
        float l = linv[r];
        float4* p = reinterpret_cast<float4*>(&Ab[(size_t)r * NK_ + c]);
        float4 v = *p;
        v.x *= l; v.y *= l; v.z *= l; v.w *= l;
        *p = v;
    }
}

// ---------------------------------------------------------------------------
extern "C" void kernel_launch(void* const* d_in, const int* in_sizes, int n_in,
                              void* d_out, int out_size)
{
    const float* q  = (const float*)d_in[0];
    const float* k  = (const float*)d_in[1];
    const float* v  = (const float*)d_in[2];
    const float* Wq = (const float*)d_in[3];
    const float* bq = (const float*)d_in[4];
    const float* Wk = (const float*)d_in[5];
    const float* bk = (const float*)d_in[6];
    const float* Wv = (const float*)d_in[7];
    const float* bv = (const float*)d_in[8];
    const float* Wo = (const float*)d_in[9];
    const float* bo = (const float*)d_in[10];

    float* out = (float*)d_out;                         // [B, NQ, D]
    float* A   = out + (size_t)B_ * NQ_ * D_;           // [B, H, NQ, NK]

    float *gQ, *gK, *gV, *gctx;
    cudaGetSymbolAddress((void**)&gQ,  g_Q);
    cudaGetSymbolAddress((void**)&gK,  g_K);
    cudaGetSymbolAddress((void**)&gV,  g_V);
    cudaGetSymbolAddress((void**)&gctx, g_ctx);

    cudaFuncSetAttribute(attn_tc, cudaFuncAttributeMaxDynamicSharedMemorySize,
                         ATT_SMEM_FLOATS * 4);

    dim3 blk(256);
    proj_tc<true><<<dim3(16, 4), blk>>>(q, Wq, bq, gQ, NQ_);
    proj_tc<true><<<dim3(128, 4), blk>>>(k, Wk, bk, gK, NK_);
    proj_tc<true><<<dim3(128, 4), blk>>>(v, Wv, bv, gV, NK_);
    attn_tc<<<256, blk, ATT_SMEM_FLOATS * 4>>>(gQ, gK, gV, A, gctx);
    proj_tc<false><<<dim3(16, 4), blk>>>(gctx, Wo, bo, out, NQ_);
}

// round 6
// speedup vs baseline: 1.3008x; 1.3008x over previous
#include <cuda_runtime.h>
#include <math.h>

#define B_  4
#define H_  8
#define D_  512
#define HD_ 64
#define NQ_ 512
#define NK_ 4096

// exp(s/8) == exp2(s * 0.125 * log2(e))
#define EXPC 0.18033688011112042f

// ---------------- scratch (no-alloc rule) ----------------
__device__ float g_Q[(size_t)B_ * H_ * NQ_ * HD_];    // tf32-rounded
__device__ float g_K[(size_t)B_ * H_ * NK_ * HD_];    // tf32-rounded
__device__ float g_V[(size_t)B_ * H_ * NK_ * HD_];    // tf32-rounded
__device__ float g_ctx[(size_t)B_ * NQ_ * D_];

// ---------------- helpers ----------------
__device__ __forceinline__ unsigned f2tf32(float x) {
    unsigned r;
    asm("cvt.rna.tf32.f32 %0, %1;" : "=r"(r) : "f"(x));
    return r;
}

__device__ __forceinline__ void mma_tf32(float* d, const unsigned* a,
                                         const unsigned* b) {
    asm volatile(
        "mma.sync.aligned.m16n8k8.row.col.f32.tf32.tf32.f32 "
        "{%0,%1,%2,%3}, {%4,%5,%6,%7}, {%8,%9}, {%0,%1,%2,%3};"
        : "+f"(d[0]), "+f"(d[1]), "+f"(d[2]), "+f"(d[3])
        : "r"(a[0]), "r"(a[1]), "r"(a[2]), "r"(a[3]),
          "r"(b[0]), "r"(b[1]));
}

__device__ __forceinline__ void cpa16(unsigned dst, const void* src) {
    asm volatile("cp.async.cg.shared.global [%0], [%1], 16;\n"
                 :: "r"(dst), "l"(src));
}
__device__ __forceinline__ void cpa_commit() {
    asm volatile("cp.async.commit_group;\n" ::: "memory");
}
template <int N>
__device__ __forceinline__ void cpa_wait() {
    asm volatile("cp.async.wait_group %0;\n" :: "n"(N) : "memory");
}

// ---------------------------------------------------------------------------
// TF32 projection GEMM, cp.async 2-stage: Y = X @ W^T + bias.
// Raw fp32 staged in smem; cvt.rna.tf32 at fragment load.
// SPLIT=true also rounds outputs to tf32 bits for the attention kernel.
// ---------------------------------------------------------------------------
#define PSTG 4608   // 128*36 floats per stage per matrix

template <bool SPLIT>
__global__ __launch_bounds__(256, 2) void proj_tc(
    const float* __restrict__ X, const float* __restrict__ W,
    const float* __restrict__ bias, float* __restrict__ Y, int N_seq)
{
    extern __shared__ float psm[];
    float* Xs = psm;                 // [2][PSTG]
    float* Ws = psm + 2 * PSTG;      // [2][PSTG]

    const int tid  = threadIdx.x;
    const int lane = tid & 31;
    const int w    = tid >> 5;
    const int wm   = w >> 2;
    const int wn   = w & 3;
    const int g    = lane >> 2;
    const int t    = lane & 3;
    const int bm   = blockIdx.x * 128;
    const int bn   = blockIdx.y * 128;

    unsigned xs_u = (unsigned)__cvta_generic_to_shared(Xs);
    unsigned ws_u = (unsigned)__cvta_generic_to_shared(Ws);

    float acc[4][4][4];
#pragma unroll
    for (int mi = 0; mi < 4; mi++)
#pragma unroll
        for (int nj = 0; nj < 4; nj++)
#pragma unroll
            for (int rr = 0; rr < 4; rr++) acc[mi][nj][rr] = 0.0f;

    // prefetch stage 0 (k0 = 0)
#pragma unroll
    for (int it = 0; it < 4; it++) {
        int i = it * 256 + tid;
        int r = i >> 3, c = (i & 7) * 4;
        cpa16(xs_u + (r * 36 + c) * 4, X + (size_t)(bm + r) * D_ + c);
        cpa16(ws_u + (r * 36 + c) * 4, W + (size_t)(bn + r) * D_ + c);
    }
    cpa_commit();

    for (int ki = 0; ki < 16; ki++) {
        cpa_wait<0>();
        __syncthreads();
        if (ki < 15) {
            int st = ((ki + 1) & 1) * PSTG;
            int k0 = (ki + 1) * 32;
#pragma unroll
            for (int it = 0; it < 4; it++) {
                int i = it * 256 + tid;
                int r = i >> 3, c = (i & 7) * 4;
                cpa16(xs_u + (st + r * 36 + c) * 4,
                      X + (size_t)(bm + r) * D_ + k0 + c);
                cpa16(ws_u + (st + r * 36 + c) * 4,
                      W + (size_t)(bn + r) * D_ + k0 + c);
            }
            cpa_commit();
        }
        const float* Xc = Xs + (ki & 1) * PSTG;
        const float* Wc = Ws + (ki & 1) * PSTG;

#pragma unroll
        for (int k8 = 0; k8 < 4; k8++) {
            unsigned a[4][4], b[4][2];
            int kk = k8 * 8 + t;
#pragma unroll
            for (int mi = 0; mi < 4; mi++) {
                int r = wm * 64 + mi * 16 + g;
                a[mi][0] = f2tf32(Xc[r * 36 + kk]);
                a[mi][1] = f2tf32(Xc[(r + 8) * 36 + kk]);
                a[mi][2] = f2tf32(Xc[r * 36 + kk + 4]);
                a[mi][3] = f2tf32(Xc[(r + 8) * 36 + kk + 4]);
            }
#pragma unroll
            for (int nj = 0; nj < 4; nj++) {
                int n = wn * 32 + nj * 8 + g;
                b[nj][0] = f2tf32(Wc[n * 36 + kk]);
                b[nj][1] = f2tf32(Wc[n * 36 + kk + 4]);
            }
#pragma unroll
            for (int mi = 0; mi < 4; mi++)
#pragma unroll
                for (int nj = 0; nj < 4; nj++)
                    mma_tf32(acc[mi][nj], a[mi], b[nj]);
        }
    }

#pragma unroll
    for (int mi = 0; mi < 4; mi++) {
#pragma unroll
        for (int nj = 0; nj < 4; nj++) {
            int n = bn + wn * 32 + nj * 8 + t * 2;
            float b0 = bias[n], b1 = bias[n + 1];
#pragma unroll
            for (int rr = 0; rr < 2; rr++) {
                int m = bm + wm * 64 + mi * 16 + g + rr * 8;
                float v0 = acc[mi][nj][rr * 2] + b0;
                float v1 = acc[mi][nj][rr * 2 + 1] + b1;
                float2 v;
                if (SPLIT) {
                    v = make_float2(__uint_as_float(f2tf32(v0)),
                                    __uint_as_float(f2tf32(v1)));
                    int bb = m / N_seq;
                    int s  = m - bb * N_seq;
                    int h  = n >> 6;
                    int hd = n & 63;
                    *reinterpret_cast<float2*>(
                        &Y[((((size_t)bb * H_ + h) * N_seq + s) << 6) + hd]) = v;
                } else {
                    v = make_float2(v0, v1);
                    *reinterpret_cast<float2*>(&Y[(size_t)m * D_ + n]) = v;
                }
            }
        }
    }
}

// ---------------------------------------------------------------------------
// Two-phase TF32 fused attention, max-free softmax, warp-owns-full-K-rows.
// CTA = (bh, qt): 64 q rows, 4 warps (warp = 16 q rows x 64 ktile cols).
// Phase 1: S-mma + exp row sums (warp-local, register-resident 1/l).
// Phase 2: S-mma again, normalized A written ONCE, PV-mma with A-fragments
//          built via shfl (no smem P, no cross-warp barrier).
// K/V double-buffered via cp.async; one __syncthreads per ktile.
// ---------------------------------------------------------------------------
#define STRK 68
#define STRV 72
#define KBUF 4352            // 64*68
#define VBUF 4608            // 64*72
#define ATT_SMEM_BYTES ((2 * KBUF + 2 * VBUF) * 4)   // 71680

__global__ __launch_bounds__(128, 3) void attn_tc(
    const float* __restrict__ gQ, const float* __restrict__ gK,
    const float* __restrict__ gV, float* __restrict__ A_out,
    float* __restrict__ gctx)
{
    extern __shared__ float sm[];
    float* Kb = sm;                  // [2][KBUF]
    float* Vb = sm + 2 * KBUF;       // [2][VBUF]

    const int tid  = threadIdx.x;
    const int lane = tid & 31;
    const int w    = tid >> 5;
    const int g    = lane >> 2;
    const int t    = lane & 3;
    const int bh   = blockIdx.x >> 3;
    const int qt   = blockIdx.x & 7;
    const int rw   = w * 16;

    const float* Qg = gQ + ((size_t)bh * NQ_ + qt * 64 + rw) * HD_;
    const float* Kg = gK + (size_t)bh * NK_ * HD_;
    const float* Vg = gV + (size_t)bh * NK_ * HD_;
    float* Ab = A_out + ((size_t)bh * NQ_ + qt * 64) * NK_;

    const int pr = tid >> 4;             // 0..7
    const int pc = (tid & 15) * 4;       // 0..60
    unsigned kb_u = (unsigned)__cvta_generic_to_shared(Kb);
    unsigned vb_u = (unsigned)__cvta_generic_to_shared(Vb);

    // Q fragments direct from gmem (already tf32 bits), reused all 128 iters
    unsigned qa[8][4];
#pragma unroll
    for (int k8 = 0; k8 < 8; k8++) {
        int kk = k8 * 8 + t;
        qa[k8][0] = __float_as_uint(Qg[(size_t)g * HD_ + kk]);
        qa[k8][1] = __float_as_uint(Qg[(size_t)(g + 8) * HD_ + kk]);
        qa[k8][2] = __float_as_uint(Qg[(size_t)g * HD_ + kk + 4]);
        qa[k8][3] = __float_as_uint(Qg[(size_t)(g + 8) * HD_ + kk + 4]);
    }

    // ================= PHASE 1: row sums (K only) =================
#pragma unroll
    for (int it = 0; it < 8; it++) {
        int r = it * 8 + pr;
        cpa16(kb_u + (r * STRK + pc) * 4, Kg + (size_t)r * HD_ + pc);
    }
    cpa_commit();

    float psum0 = 0.0f, psum1 = 0.0f;

    for (int kt = 0; kt < 64; kt++) {
        cpa_wait<0>();
        __syncthreads();
        if (kt < 63) {
            const float* Kn = Kg + (size_t)(kt + 1) * 64 * HD_;
            unsigned kdst = kb_u + ((kt + 1) & 1) * KBUF * 4;
#pragma unroll
            for (int it = 0; it < 8; it++) {
                int r = it * 8 + pr;
                cpa16(kdst + (r * STRK + pc) * 4, Kn + (size_t)r * HD_ + pc);
            }
            cpa_commit();
        }
        const unsigned* Ks = (const unsigned*)(Kb + (kt & 1) * KBUF);

        float s[8][4];
#pragma unroll
        for (int nj = 0; nj < 8; nj++)
#pragma unroll
            for (int rr = 0; rr < 4; rr++) s[nj][rr] = 0.0f;

#pragma unroll
        for (int k8 = 0; k8 < 8; k8++) {
            int kk = k8 * 8 + t;
#pragma unroll
            for (int nj = 0; nj < 8; nj++) {
                unsigned b[2];
                int n = nj * 8 + g;
                b[0] = Ks[n * STRK + kk];
                b[1] = Ks[n * STRK + kk + 4];
                mma_tf32(s[nj], qa[k8], b);
            }
        }

#pragma unroll
        for (int nj = 0; nj < 8; nj++) {
            psum0 += exp2f(s[nj][0] * EXPC) + exp2f(s[nj][1] * EXPC);
            psum1 += exp2f(s[nj][2] * EXPC) + exp2f(s[nj][3] * EXPC);
        }
    }

    // warp-local reduce over the 4 t-lanes -> per-row 1/l in registers
    psum0 += __shfl_xor_sync(0xffffffffu, psum0, 1);
    psum0 += __shfl_xor_sync(0xffffffffu, psum0, 2);
    psum1 += __shfl_xor_sync(0xffffffffu, psum1, 1);
    psum1 += __shfl_xor_sync(0xffffffffu, psum1, 2);
    const float li0 = 1.0f / psum0;
    const float li1 = 1.0f / psum1;

    // ================= PHASE 2: A + ctx =================
#pragma unroll
    for (int it = 0; it < 8; it++) {
        int r = it * 8 + pr;
        cpa16(kb_u + (r * STRK + pc) * 4, Kg + (size_t)r * HD_ + pc);
        cpa16(vb_u + (r * STRV + pc) * 4, Vg + (size_t)r * HD_ + pc);
    }
    cpa_commit();

    float ctx[8][4];
#pragma unroll
    for (int nj = 0; nj < 8; nj++)
#pragma unroll
        for (int rr = 0; rr < 4; rr++) ctx[nj][rr] = 0.0f;

    const int srcA = (lane & ~3) | (t >> 1);
    const int srcB = srcA + 2;
    const bool sel = (t & 1);

    for (int kt = 0; kt < 64; kt++) {
        cpa_wait<0>();
        __syncthreads();
        if (kt < 63) {
            const float* Kn = Kg + (size_t)(kt + 1) * 64 * HD_;
            const float* Vn = Vg + (size_t)(kt + 1) * 64 * HD_;
            unsigned kdst = kb_u + ((kt + 1) & 1) * KBUF * 4;
            unsigned vdst = vb_u + ((kt + 1) & 1) * VBUF * 4;
#pragma unroll
            for (int it = 0; it < 8; it++) {
                int r = it * 8 + pr;
                cpa16(kdst + (r * STRK + pc) * 4, Kn + (size_t)r * HD_ + pc);
                cpa16(vdst + (r * STRV + pc) * 4, Vn + (size_t)r * HD_ + pc);
            }
            cpa_commit();
        }
        const unsigned* Ks = (const unsigned*)(Kb + (kt & 1) * KBUF);
        const unsigned* Vs = (const unsigned*)(Vb + (kt & 1) * VBUF);

        // ---- S = Q K^T ----
        float s[8][4];
#pragma unroll
        for (int nj = 0; nj < 8; nj++)
#pragma unroll
            for (int rr = 0; rr < 4; rr++) s[nj][rr] = 0.0f;

#pragma unroll
        for (int k8 = 0; k8 < 8; k8++) {
            int kk = k8 * 8 + t;
#pragma unroll
            for (int nj = 0; nj < 8; nj++) {
                unsigned b[2];
                int n = nj * 8 + g;
                b[0] = Ks[n * STRK + kk];
                b[1] = Ks[n * STRK + kk + 4];
                mma_tf32(s[nj], qa[k8], b);
            }
        }

        // ---- normalized P: write A once, keep tf32 bits for PV ----
        unsigned u0[8], u1[8], u2[8], u3[8];
#pragma unroll
        for (int nj = 0; nj < 8; nj++) {
            float p0 = exp2f(s[nj][0] * EXPC) * li0;
            float p1 = exp2f(s[nj][1] * EXPC) * li0;
            float p2 = exp2f(s[nj][2] * EXPC) * li1;
            float p3 = exp2f(s[nj][3] * EXPC) * li1;
            int col = kt * 64 + nj * 8 + t * 2;
            *reinterpret_cast<float2*>(
                &Ab[(size_t)(rw + g) * NK_ + col]) = make_float2(p0, p1);
            *reinterpret_cast<float2*>(
                &Ab[(size_t)(rw + g + 8) * NK_ + col]) = make_float2(p2, p3);
            u0[nj] = f2tf32(p0);
            u1[nj] = f2tf32(p1);
            u2[nj] = f2tf32(p2);
            u3[nj] = f2tf32(p3);
        }

        // ---- ctx += P V : A-frags via shfl (warp-local) ----
#pragma unroll
        for (int c = 0; c < 8; c++) {
            unsigned x0 = __shfl_sync(0xffffffffu, u0[c], srcA);
            unsigned x1 = __shfl_sync(0xffffffffu, u1[c], srcA);
            unsigned y0 = __shfl_sync(0xffffffffu, u0[c], srcB);
            unsigned y1 = __shfl_sync(0xffffffffu, u1[c], srcB);
            unsigned z0 = __shfl_sync(0xffffffffu, u2[c], srcA);
            unsigned z1 = __shfl_sync(0xffffffffu, u3[c], srcA);
            unsigned w0 = __shfl_sync(0xffffffffu, u2[c], srcB);
            unsigned w1 = __shfl_sync(0xffffffffu, u3[c], srcB);
            unsigned pa[4];
            pa[0] = sel ? x1 : x0;   // row g,   col t
            pa[1] = sel ? z1 : z0;   // row g+8, col t
            pa[2] = sel ? y1 : y0;   // row g,   col t+4
            pa[3] = sel ? w1 : w0;   // row g+8, col t+4
            int k0 = c * 8 + t;
#pragma unroll
            for (int nj = 0; nj < 8; nj++) {
                unsigned b[2];
                int n = nj * 8 + g;
                b[0] = Vs[k0 * STRV + n];
                b[1] = Vs[(k0 + 4) * STRV + n];
                mma_tf32(ctx[nj], pa, b);
            }
        }
    }

    // ---- write ctx (already normalized) ----
    const int b0 = bh >> 3;
    const int h  = bh & 7;
#pragma unroll
    for (int nj = 0; nj < 8; nj++) {
        int hd = nj * 8 + t * 2;
#pragma unroll
        for (int rr = 0; rr < 2; rr++) {
            int q = qt * 64 + rw + g + rr * 8;
            float2 v = make_float2(ctx[nj][rr * 2], ctx[nj][rr * 2 + 1]);
            *reinterpret_cast<float2*>(
                &gctx[((size_t)b0 * NQ_ + q) * D_ + h * 64 + hd]) = v;
        }
    }
}

// ---------------------------------------------------------------------------
extern "C" void kernel_launch(void* const* d_in, const int* in_sizes, int n_in,
                              void* d_out, int out_size)
{
    const float* q  = (const float*)d_in[0];
    const float* k  = (const float*)d_in[1];
    const float* v  = (const float*)d_in[2];
    const float* Wq = (const float*)d_in[3];
    const float* bq = (const float*)d_in[4];
    const float* Wk = (const float*)d_in[5];
    const float* bk = (const float*)d_in[6];
    const float* Wv = (const float*)d_in[7];
    const float* bv = (const float*)d_in[8];
    const float* Wo = (const float*)d_in[9];
    const float* bo = (const float*)d_in[10];

    float* out = (float*)d_out;                         // [B, NQ, D]
    float* A   = out + (size_t)B_ * NQ_ * D_;           // [B, H, NQ, NK]

    float *gQ, *gK, *gV, *gctx;
    cudaGetSymbolAddress((void**)&gQ,  g_Q);
    cudaGetSymbolAddress((void**)&gK,  g_K);
    cudaGetSymbolAddress((void**)&gV,  g_V);
    cudaGetSymbolAddress((void**)&gctx, g_ctx);

    const int proj_smem = 4 * PSTG * 4;   // 73728 B
    cudaFuncSetAttribute(proj_tc<true>,
        cudaFuncAttributeMaxDynamicSharedMemorySize, proj_smem);
    cudaFuncSetAttribute(proj_tc<false>,
        cudaFuncAttributeMaxDynamicSharedMemorySize, proj_smem);
    cudaFuncSetAttribute(attn_tc,
        cudaFuncAttributeMaxDynamicSharedMemorySize, ATT_SMEM_BYTES);

    dim3 blk(256);
    proj_tc<true><<<dim3(16, 4), blk, proj_smem>>>(q, Wq, bq, gQ, NQ_);
    proj_tc<true><<<dim3(128, 4), blk, proj_smem>>>(k, Wk, bk, gK, NK_);
    proj_tc<true><<<dim3(128, 4), blk, proj_smem>>>(v, Wv, bv, gV, NK_);
    attn_tc<<<256, 128, ATT_SMEM_BYTES>>>(gQ, gK, gV, A, gctx);
    proj_tc<false><<<dim3(16, 4), blk, proj_smem>>>(gctx, Wo, bo, out, NQ_);
}

// round 8
// speedup vs baseline: 1.4632x; 1.1248x over previous
#include <cuda_runtime.h>
#include <math.h>

#define B_  4
#define H_  8
#define D_  512
#define HD_ 64
#define NQ_ 512
#define NK_ 4096

// exp(s/8) == exp2(s * 0.125 * log2(e))
#define EXPC 0.18033688011112042f

// ---------------- scratch (no-alloc rule) ----------------
__device__ float g_Q[(size_t)B_ * H_ * NQ_ * HD_];    // [bh][s][hd] tf32 bits
__device__ float g_K[(size_t)B_ * H_ * NK_ * HD_];    // packed (hd,hd+4) pairs
__device__ float g_V[(size_t)B_ * H_ * NK_ * HD_];    // packed (kv,kv+4) pairs
__device__ float g_ctx[(size_t)B_ * NQ_ * D_];

// ---------------- helpers ----------------
__device__ __forceinline__ unsigned f2tf32(float x) {
    unsigned r;
    asm("cvt.rna.tf32.f32 %0, %1;" : "=r"(r) : "f"(x));
    return r;
}

__device__ __forceinline__ void mma_tf32(float* d, const unsigned* a,
                                         const unsigned* b) {
    asm volatile(
        "mma.sync.aligned.m16n8k8.row.col.f32.tf32.tf32.f32 "
        "{%0,%1,%2,%3}, {%4,%5,%6,%7}, {%8,%9}, {%0,%1,%2,%3};"
        : "+f"(d[0]), "+f"(d[1]), "+f"(d[2]), "+f"(d[3])
        : "r"(a[0]), "r"(a[1]), "r"(a[2]), "r"(a[3]),
          "r"(b[0]), "r"(b[1]));
}

__device__ __forceinline__ void cpa16(unsigned dst, const void* src) {
    asm volatile("cp.async.cg.shared.global [%0], [%1], 16;\n"
                 :: "r"(dst), "l"(src));
}
__device__ __forceinline__ void cpa_commit() {
    asm volatile("cp.async.commit_group;\n" ::: "memory");
}
template <int N>
__device__ __forceinline__ void cpa_wait() {
    asm volatile("cp.async.wait_group %0;\n" :: "n"(N) : "memory");
}

// ---------------------------------------------------------------------------
// Fused Q/K/V projection (one launch): Y = X @ W^T + bias, tf32-rounded.
//   mode 0 (Q): [bh][s][hd] plain
//   mode 1 (K): packed pairs over hd:  Kp[bh][s][j].{x,y} = K[s][hd], K[s][hd+4]
//               j = (hd>>3)*4 + (hd&3)
//   mode 2 (V): packed pairs over kv:  Vp[bh][kt][sl][hd].{x,y} = V[kv],V[kv+4]
//               sl = ((kv&63)>>3)*4 + (kv&3), half = (kv>>2)&1
// ---------------------------------------------------------------------------
#define PSTG 4608   // 128*36 floats per stage per matrix

__global__ __launch_bounds__(256, 2) void proj_qkv(
    const float* __restrict__ Xq, const float* __restrict__ Wq, const float* __restrict__ bq,
    const float* __restrict__ Xk, const float* __restrict__ Wk, const float* __restrict__ bk,
    const float* __restrict__ Xv, const float* __restrict__ Wv, const float* __restrict__ bv,
    float* __restrict__ Yq, float* __restrict__ Yk, float* __restrict__ Yv)
{
    extern __shared__ float psm[];
    float* Xs = psm;
    float* Ws = psm + 2 * PSTG;

    const float *X, *W, *bias;
    float* Y;
    int mode, bxt, N_seq;
    if (blockIdx.x < 16)       { X = Xq; W = Wq; bias = bq; Y = Yq; mode = 0; bxt = blockIdx.x;      N_seq = NQ_; }
    else if (blockIdx.x < 144) { X = Xk; W = Wk; bias = bk; Y = Yk; mode = 1; bxt = blockIdx.x - 16; N_seq = NK_; }
    else                       { X = Xv; W = Wv; bias = bv; Y = Yv; mode = 2; bxt = blockIdx.x - 144; N_seq = NK_; }

    const int tid  = threadIdx.x;
    const int lane = tid & 31;
    const int w    = tid >> 5;
    const int wm   = w >> 2;
    const int wn   = w & 3;
    const int g    = lane >> 2;
    const int t    = lane & 3;
    const int bm   = bxt * 128;
    const int bn   = blockIdx.y * 128;

    unsigned xs_u = (unsigned)__cvta_generic_to_shared(Xs);
    unsigned ws_u = (unsigned)__cvta_generic_to_shared(Ws);

    float acc[4][4][4];
#pragma unroll
    for (int mi = 0; mi < 4; mi++)
#pragma unroll
        for (int nj = 0; nj < 4; nj++)
#pragma unroll
            for (int rr = 0; rr < 4; rr++) acc[mi][nj][rr] = 0.0f;

#pragma unroll
    for (int it = 0; it < 4; it++) {
        int i = it * 256 + tid;
        int r = i >> 3, c = (i & 7) * 4;
        cpa16(xs_u + (r * 36 + c) * 4, X + (size_t)(bm + r) * D_ + c);
        cpa16(ws_u + (r * 36 + c) * 4, W + (size_t)(bn + r) * D_ + c);
    }
    cpa_commit();

    for (int ki = 0; ki < 16; ki++) {
        cpa_wait<0>();
        __syncthreads();
        if (ki < 15) {
            int st = ((ki + 1) & 1) * PSTG;
            int k0 = (ki + 1) * 32;
#pragma unroll
            for (int it = 0; it < 4; it++) {
                int i = it * 256 + tid;
                int r = i >> 3, c = (i & 7) * 4;
                cpa16(xs_u + (st + r * 36 + c) * 4,
                      X + (size_t)(bm + r) * D_ + k0 + c);
                cpa16(ws_u + (st + r * 36 + c) * 4,
                      W + (size_t)(bn + r) * D_ + k0 + c);
            }
            cpa_commit();
        }
        const float* Xc = Xs + (ki & 1) * PSTG;
        const float* Wc = Ws + (ki & 1) * PSTG;

#pragma unroll
        for (int k8 = 0; k8 < 4; k8++) {
            unsigned a[4][4], b[4][2];
            int kk = k8 * 8 + t;
#pragma unroll
            for (int mi = 0; mi < 4; mi++) {
                int r = wm * 64 + mi * 16 + g;
                a[mi][0] = f2tf32(Xc[r * 36 + kk]);
                a[mi][1] = f2tf32(Xc[(r + 8) * 36 + kk]);
                a[mi][2] = f2tf32(Xc[r * 36 + kk + 4]);
                a[mi][3] = f2tf32(Xc[(r + 8) * 36 + kk + 4]);
            }
#pragma unroll
            for (int nj = 0; nj < 4; nj++) {
                int n = wn * 32 + nj * 8 + g;
                b[nj][0] = f2tf32(Wc[n * 36 + kk]);
                b[nj][1] = f2tf32(Wc[n * 36 + kk + 4]);
            }
#pragma unroll
            for (int mi = 0; mi < 4; mi++)
#pragma unroll
                for (int nj = 0; nj < 4; nj++)
                    mma_tf32(acc[mi][nj], a[mi], b[nj]);
        }
    }

#pragma unroll
    for (int mi = 0; mi < 4; mi++) {
#pragma unroll
        for (int nj = 0; nj < 4; nj++) {
            int n = bn + wn * 32 + nj * 8 + t * 2;
            float b0 = bias[n], b1 = bias[n + 1];
#pragma unroll
            for (int rr = 0; rr < 2; rr++) {
                int m = bm + wm * 64 + mi * 16 + g + rr * 8;
                float v0 = __uint_as_float(f2tf32(acc[mi][nj][rr * 2] + b0));
                float v1 = __uint_as_float(f2tf32(acc[mi][nj][rr * 2 + 1] + b1));
                int s  = m & (N_seq - 1);
                int bb = m / N_seq;        // N_seq is power of 2 but keep simple
                int h  = n >> 6;
                int hd = n & 63;
                int bh = bb * H_ + h;
                if (mode == 0) {
                    *reinterpret_cast<float2*>(
                        &Y[(((size_t)bh * NQ_ + s) << 6) + hd]) = make_float2(v0, v1);
                } else if (mode == 1) {
                    size_t base = (((size_t)bh * NK_ + s) << 6);
                    int j0 = (hd >> 3) * 4 + (hd & 3);
                    int hf = (hd >> 2) & 1;
                    Y[base + j0 * 2 + hf]       = v0;   // hd
                    Y[base + (j0 + 1) * 2 + hf] = v1;   // hd+1 (same half, j+1)
                } else {
                    int stile = s >> 6;
                    int sl = ((s & 63) >> 3) * 4 + (s & 3);
                    int hf = (s >> 2) & 1;
                    size_t base = ((((size_t)bh * (NK_ / 64) + stile) * 32 + sl) << 7);
                    Y[base + hd * 2 + hf]       = v0;
                    Y[base + (hd + 1) * 2 + hf] = v1;
                }
            }
        }
    }
}

// ---------------------------------------------------------------------------
// Output projection (plain fp32 epilogue), cp.async 2-stage.
// ---------------------------------------------------------------------------
__global__ __launch_bounds__(256, 2) void proj_out(
    const float* __restrict__ X, const float* __restrict__ W,
    const float* __restrict__ bias, float* __restrict__ Y)
{
    extern __shared__ float psm[];
    float* Xs = psm;
    float* Ws = psm + 2 * PSTG;

    const int tid  = threadIdx.x;
    const int lane = tid & 31;
    const int w    = tid >> 5;
    const int wm   = w >> 2;
    const int wn   = w & 3;
    const int g    = lane >> 2;
    const int t    = lane & 3;
    const int bm   = blockIdx.x * 128;
    const int bn   = blockIdx.y * 128;

    unsigned xs_u = (unsigned)__cvta_generic_to_shared(Xs);
    unsigned ws_u = (unsigned)__cvta_generic_to_shared(Ws);

    float acc[4][4][4];
#pragma unroll
    for (int mi = 0; mi < 4; mi++)
#pragma unroll
        for (int nj = 0; nj < 4; nj++)
#pragma unroll
            for (int rr = 0; rr < 4; rr++) acc[mi][nj][rr] = 0.0f;

#pragma unroll
    for (int it = 0; it < 4; it++) {
        int i = it * 256 + tid;
        int r = i >> 3, c = (i & 7) * 4;
        cpa16(xs_u + (r * 36 + c) * 4, X + (size_t)(bm + r) * D_ + c);
        cpa16(ws_u + (r * 36 + c) * 4, W + (size_t)(bn + r) * D_ + c);
    }
    cpa_commit();

    for (int ki = 0; ki < 16; ki++) {
        cpa_wait<0>();
        __syncthreads();
        if (ki < 15) {
            int st = ((ki + 1) & 1) * PSTG;
            int k0 = (ki + 1) * 32;
#pragma unroll
            for (int it = 0; it < 4; it++) {
                int i = it * 256 + tid;
                int r = i >> 3, c = (i & 7) * 4;
                cpa16(xs_u + (st + r * 36 + c) * 4,
                      X + (size_t)(bm + r) * D_ + k0 + c);
                cpa16(ws_u + (st + r * 36 + c) * 4,
                      W + (size_t)(bn + r) * D_ + k0 + c);
            }
            cpa_commit();
        }
        const float* Xc = Xs + (ki & 1) * PSTG;
        const float* Wc = Ws + (ki & 1) * PSTG;

#pragma unroll
        for (int k8 = 0; k8 < 4; k8++) {
            unsigned a[4][4], b[4][2];
            int kk = k8 * 8 + t;
#pragma unroll
            for (int mi = 0; mi < 4; mi++) {
                int r = wm * 64 + mi * 16 + g;
                a[mi][0] = f2tf32(Xc[r * 36 + kk]);
                a[mi][1] = f2tf32(Xc[(r + 8) * 36 + kk]);
                a[mi][2] = f2tf32(Xc[r * 36 + kk + 4]);
                a[mi][3] = f2tf32(Xc[(r + 8) * 36 + kk + 4]);
            }
#pragma unroll
            for (int nj = 0; nj < 4; nj++) {
                int n = wn * 32 + nj * 8 + g;
                b[nj][0] = f2tf32(Wc[n * 36 + kk]);
                b[nj][1] = f2tf32(Wc[n * 36 + kk + 4]);
            }
#pragma unroll
            for (int mi = 0; mi < 4; mi++)
#pragma unroll
                for (int nj = 0; nj < 4; nj++)
                    mma_tf32(acc[mi][nj], a[mi], b[nj]);
        }
    }

#pragma unroll
    for (int mi = 0; mi < 4; mi++) {
#pragma unroll
        for (int nj = 0; nj < 4; nj++) {
            int n = bn + wn * 32 + nj * 8 + t * 2;
            float b0 = bias[n], b1 = bias[n + 1];
#pragma unroll
            for (int rr = 0; rr < 2; rr++) {
                int m = bm + wm * 64 + mi * 16 + g + rr * 8;
                *reinterpret_cast<float2*>(&Y[(size_t)m * D_ + n]) =
                    make_float2(acc[mi][nj][rr * 2] + b0,
                                acc[mi][nj][rr * 2 + 1] + b1);
            }
        }
    }
}

// ---------------------------------------------------------------------------
// Two-phase TF32 fused attention with packed LDS.64 fragment loads.
// CTA = (bh, qt): 64 q rows, 4 warps (16 q rows x full 64 ktile each).
// ---------------------------------------------------------------------------
#define KROWB 288                    // 36 float2 per row
#define KBUFB (64 * KROWB)           // 18432 B
#define VROWB 544                    // 68 float2 per row
#define VBUFB (32 * VROWB)           // 17408 B
#define ATT_SMEM_BYTES (2 * KBUFB + 2 * VBUFB)   // 71680

__global__ __launch_bounds__(128, 3) void attn_tc(
    const float* __restrict__ gQ, const float* __restrict__ gK,
    const float* __restrict__ gV, float* __restrict__ A_out,
    float* __restrict__ gctx)
{
    extern __shared__ char smc[];
    char* Kb = smc;                  // [2][KBUFB]
    char* Vb = smc + 2 * KBUFB;      // [2][VBUFB]

    const int tid  = threadIdx.x;
    const int lane = tid & 31;
    const int w    = tid >> 5;
    const int g    = lane >> 2;
    const int t    = lane & 3;
    const int bh   = blockIdx.x >> 3;
    const int qt   = blockIdx.x & 7;
    const int rw   = w * 16;

    const float*  Qg  = gQ + ((size_t)bh * NQ_ + qt * 64 + rw) * HD_;
    const float2* Kg2 = (const float2*)gK + (size_t)bh * NK_ * 32;
    const float2* Vg2 = (const float2*)gV + (size_t)bh * NK_ * 32;
    float* Ab = A_out + ((size_t)bh * NQ_ + qt * 64) * NK_;

    unsigned kb_u = (unsigned)__cvta_generic_to_shared(Kb);
    unsigned vb_u = (unsigned)__cvta_generic_to_shared(Vb);

    // Q fragments from gmem (tf32 bits), reused for all 128 tile iterations
    unsigned qa[8][4];
#pragma unroll
    for (int k8 = 0; k8 < 8; k8++) {
        int kk = k8 * 8 + t;
        qa[k8][0] = __float_as_uint(Qg[(size_t)g * HD_ + kk]);
        qa[k8][1] = __float_as_uint(Qg[(size_t)(g + 8) * HD_ + kk]);
        qa[k8][2] = __float_as_uint(Qg[(size_t)g * HD_ + kk + 4]);
        qa[k8][3] = __float_as_uint(Qg[(size_t)(g + 8) * HD_ + kk + 4]);
    }

    // ================= PHASE 1: row sums (K only) =================
#pragma unroll
    for (int it = 0; it < 8; it++) {
        int i = it * 128 + tid;              // 1024 chunks
        int r = i >> 4, c = i & 15;
        cpa16(kb_u + r * KROWB + c * 16, Kg2 + (size_t)r * 32 + c * 2);
    }
    cpa_commit();

    float psum0 = 0.0f, psum1 = 0.0f;

    for (int kt = 0; kt < 64; kt++) {
        cpa_wait<0>();
        __syncthreads();
        if (kt < 63) {
            const float2* Kn = Kg2 + (size_t)(kt + 1) * 64 * 32;
            unsigned kdst = kb_u + ((kt + 1) & 1) * KBUFB;
#pragma unroll
            for (int it = 0; it < 8; it++) {
                int i = it * 128 + tid;
                int r = i >> 4, c = i & 15;
                cpa16(kdst + r * KROWB + c * 16, Kn + (size_t)r * 32 + c * 2);
            }
            cpa_commit();
        }
        const float2* Ks2 = (const float2*)(Kb + (kt & 1) * KBUFB);

        float s[8][4];
#pragma unroll
        for (int nj = 0; nj < 8; nj++)
#pragma unroll
            for (int rr = 0; rr < 4; rr++) s[nj][rr] = 0.0f;

#pragma unroll
        for (int k8 = 0; k8 < 8; k8++) {
#pragma unroll
            for (int nj = 0; nj < 8; nj++) {
                float2 p = Ks2[(nj * 8 + g) * 36 + k8 * 4 + t];
                unsigned b[2] = { __float_as_uint(p.x), __float_as_uint(p.y) };
                mma_tf32(s[nj], qa[k8], b);
            }
        }

#pragma unroll
        for (int nj = 0; nj < 8; nj++) {
            psum0 += exp2f(s[nj][0] * EXPC) + exp2f(s[nj][1] * EXPC);
            psum1 += exp2f(s[nj][2] * EXPC) + exp2f(s[nj][3] * EXPC);
        }
    }

    psum0 += __shfl_xor_sync(0xffffffffu, psum0, 1);
    psum0 += __shfl_xor_sync(0xffffffffu, psum0, 2);
    psum1 += __shfl_xor_sync(0xffffffffu, psum1, 1);
    psum1 += __shfl_xor_sync(0xffffffffu, psum1, 2);
    const float li0 = 1.0f / psum0;
    const float li1 = 1.0f / psum1;

    // ================= PHASE 2: A + ctx =================
#pragma unroll
    for (int it = 0; it < 8; it++) {
        int i = it * 128 + tid;
        int r = i >> 4, c = i & 15;
        cpa16(kb_u + r * KROWB + c * 16, Kg2 + (size_t)r * 32 + c * 2);
    }
#pragma unroll
    for (int it = 0; it < 8; it++) {
        int i = it * 128 + tid;
        int r = i >> 5, c = i & 31;
        cpa16(vb_u + r * VROWB + c * 16, Vg2 + (size_t)r * 64 + c * 2);
    }
    cpa_commit();

    float ctx[8][4];
#pragma unroll
    for (int nj = 0; nj < 8; nj++)
#pragma unroll
        for (int rr = 0; rr < 4; rr++) ctx[nj][rr] = 0.0f;

    const int srcA = (lane & ~3) | (t >> 1);
    const int srcB = srcA + 2;
    const bool sel = (t & 1);

    for (int kt = 0; kt < 64; kt++) {
        cpa_wait<0>();
        __syncthreads();
        if (kt < 63) {
            const float2* Kn = Kg2 + (size_t)(kt + 1) * 64 * 32;
            const float2* Vn = Vg2 + (size_t)(kt + 1) * 32 * 64;
            unsigned kdst = kb_u + ((kt + 1) & 1) * KBUFB;
            unsigned vdst = vb_u + ((kt + 1) & 1) * VBUFB;
#pragma unroll
            for (int it = 0; it < 8; it++) {
                int i = it * 128 + tid;
                int r = i >> 4, c = i & 15;
                cpa16(kdst + r * KROWB + c * 16, Kn + (size_t)r * 32 + c * 2);
            }
#pragma unroll
            for (int it = 0; it < 8; it++) {
                int i = it * 128 + tid;
                int r = i >> 5, c = i & 31;
                cpa16(vdst + r * VROWB + c * 16, Vn + (size_t)r * 64 + c * 2);
            }
            cpa_commit();
        }
        const float2* Ks2 = (const float2*)(Kb + (kt & 1) * KBUFB);
        const float2* Vs2 = (const float2*)(Vb + (kt & 1) * VBUFB);

        // ---- S = Q K^T ----
        float s[8][4];
#pragma unroll
        for (int nj = 0; nj < 8; nj++)
#pragma unroll
            for (int rr = 0; rr < 4; rr++) s[nj][rr] = 0.0f;

#pragma unroll
        for (int k8 = 0; k8 < 8; k8++) {
#pragma unroll
            for (int nj = 0; nj < 8; nj++) {
                float2 p = Ks2[(nj * 8 + g) * 36 + k8 * 4 + t];
                unsigned b[2] = { __float_as_uint(p.x), __float_as_uint(p.y) };
                mma_tf32(s[nj], qa[k8], b);
            }
        }

        // ---- normalized P: write A once, keep tf32 bits for PV ----
        unsigned u0[8], u1[8], u2[8], u3[8];
#pragma unroll
        for (int nj = 0; nj < 8; nj++) {
            float p0 = exp2f(s[nj][0] * EXPC) * li0;
            float p1 = exp2f(s[nj][1] * EXPC) * li0;
            float p2 = exp2f(s[nj][2] * EXPC) * li1;
            float p3 = exp2f(s[nj][3] * EXPC) * li1;
            int col = kt * 64 + nj * 8 + t * 2;
            *reinterpret_cast<float2*>(
                &Ab[(size_t)(rw + g) * NK_ + col]) = make_float2(p0, p1);
            *reinterpret_cast<float2*>(
                &Ab[(size_t)(rw + g + 8) * NK_ + col]) = make_float2(p2, p3);
            u0[nj] = f2tf32(p0);
            u1[nj] = f2tf32(p1);
            u2[nj] = f2tf32(p2);
            u3[nj] = f2tf32(p3);
        }

        // ---- ctx += P V : A-frags via shfl (warp-local) ----
#pragma unroll
        for (int c = 0; c < 8; c++) {
            unsigned x0 = __shfl_sync(0xffffffffu, u0[c], srcA);
            unsigned x1 = __shfl_sync(0xffffffffu, u1[c], srcA);
            unsigned y0 = __shfl_sync(0xffffffffu, u0[c], srcB);
            unsigned y1 = __shfl_sync(0xffffffffu, u1[c], srcB);
            unsigned z0 = __shfl_sync(0xffffffffu, u2[c], srcA);
            unsigned z1 = __shfl_sync(0xffffffffu, u3[c], srcA);
            unsigned w0 = __shfl_sync(0xffffffffu, u2[c], srcB);
            unsigned w1 = __shfl_sync(0xffffffffu, u3[c], srcB);
            unsigned pa[4];
            pa[0] = sel ? x1 : x0;
            pa[1] = sel ? z1 : z0;
            pa[2] = sel ? y1 : y0;
            pa[3] = sel ? w1 : w0;
#pragma unroll
            for (int nj = 0; nj < 8; nj++) {
                float2 p = Vs2[(c * 4 + t) * 68 + nj * 8 + g];
                unsigned b[2] = { __float_as_uint(p.x), __float_as_uint(p.y) };
                mma_tf32(ctx[nj], pa, b);
            }
        }
    }

    // ---- write ctx (already normalized) ----
    const int b0 = bh >> 3;
    const int h  = bh & 7;
#pragma unroll
    for (int nj = 0; nj < 8; nj++) {
        int hd = nj * 8 + t * 2;
#pragma unroll
        for (int rr = 0; rr < 2; rr++) {
            int q = qt * 64 + rw + g + rr * 8;
            float2 v = make_float2(ctx[nj][rr * 2], ctx[nj][rr * 2 + 1]);
            *reinterpret_cast<float2*>(
                &gctx[((size_t)b0 * NQ_ + q) * D_ + h * 64 + hd]) = v;
        }
    }
}

// ---------------------------------------------------------------------------
extern "C" void kernel_launch(void* const* d_in, const int* in_sizes, int n_in,
                              void* d_out, int out_size)
{
    const float* q  = (const float*)d_in[0];
    const float* k  = (const float*)d_in[1];
    const float* v  = (const float*)d_in[2];
    const float* Wq = (const float*)d_in[3];
    const float* bq = (const float*)d_in[4];
    const float* Wk = (const float*)d_in[5];
    const float* bk = (const float*)d_in[6];
    const float* Wv = (const float*)d_in[7];
    const float* bv = (const float*)d_in[8];
    const float* Wo = (const float*)d_in[9];
    const float* bo = (const float*)d_in[10];

    float* out = (float*)d_out;                         // [B, NQ, D]
    float* A   = out + (size_t)B_ * NQ_ * D_;           // [B, H, NQ, NK]

    float *gQ, *gK, *gV, *gctx;
    cudaGetSymbolAddress((void**)&gQ,  g_Q);
    cudaGetSymbolAddress((void**)&gK,  g_K);
    cudaGetSymbolAddress((void**)&gV,  g_V);
    cudaGetSymbolAddress((void**)&gctx, g_ctx);

    const int proj_smem = 4 * PSTG * 4;   // 73728 B
    cudaFuncSetAttribute(proj_qkv,
        cudaFuncAttributeMaxDynamicSharedMemorySize, proj_smem);
    cudaFuncSetAttribute(proj_out,
        cudaFuncAttributeMaxDynamicSharedMemorySize, proj_smem);
    cudaFuncSetAttribute(attn_tc,
        cudaFuncAttributeMaxDynamicSharedMemorySize, ATT_SMEM_BYTES);

    proj_qkv<<<dim3(272, 4), 256, proj_smem>>>(
        q, Wq, bq, k, Wk, bk, v, Wv, bv, gQ, gK, gV);
    attn_tc<<<256, 128, ATT_SMEM_BYTES>>>(gQ, gK, gV, A, gctx);
    proj_out<<<dim3(16, 4), 256, proj_smem>>>(gctx, Wo, bo, out);
}

// round 9
// speedup vs baseline: 1.5491x; 1.0587x over previous
#include <cuda_runtime.h>
#include <math.h>

#define B_  4
#define H_  8
#define D_  512
#define HD_ 64
#define NQ_ 512
#define NK_ 4096

// exp(s/8) == exp2(s * 0.125 * log2(e))
#define EXPC 0.18033688011112042f

// ---------------- scratch (no-alloc rule) ----------------
__device__ float g_Q[(size_t)B_ * H_ * NQ_ * HD_];    // [bh][s][hd] tf32 bits
__device__ float g_K[(size_t)B_ * H_ * NK_ * HD_];    // k8-pair packed (see proj)
__device__ float g_V[(size_t)B_ * H_ * NK_ * HD_];    // c-pair packed (see proj)
__device__ float g_ctx[(size_t)B_ * NQ_ * D_];

// ---------------- helpers ----------------
__device__ __forceinline__ unsigned f2tf32(float x) {
    unsigned r;
    asm("cvt.rna.tf32.f32 %0, %1;" : "=r"(r) : "f"(x));
    return r;
}

__device__ __forceinline__ void mma_tf32(float* d, const unsigned* a,
                                         const unsigned* b) {
    asm volatile(
        "mma.sync.aligned.m16n8k8.row.col.f32.tf32.tf32.f32 "
        "{%0,%1,%2,%3}, {%4,%5,%6,%7}, {%8,%9}, {%0,%1,%2,%3};"
        : "+f"(d[0]), "+f"(d[1]), "+f"(d[2]), "+f"(d[3])
        : "r"(a[0]), "r"(a[1]), "r"(a[2]), "r"(a[3]),
          "r"(b[0]), "r"(b[1]));
}

__device__ __forceinline__ void mma_tf32_u(float* d, const unsigned* a,
                                           unsigned b0, unsigned b1) {
    asm volatile(
        "mma.sync.aligned.m16n8k8.row.col.f32.tf32.tf32.f32 "
        "{%0,%1,%2,%3}, {%4,%5,%6,%7}, {%8,%9}, {%0,%1,%2,%3};"
        : "+f"(d[0]), "+f"(d[1]), "+f"(d[2]), "+f"(d[3])
        : "r"(a[0]), "r"(a[1]), "r"(a[2]), "r"(a[3]),
          "r"(b0), "r"(b1));
}

__device__ __forceinline__ void cpa16(unsigned dst, const void* src) {
    asm volatile("cp.async.cg.shared.global [%0], [%1], 16;\n"
                 :: "r"(dst), "l"(src));
}
__device__ __forceinline__ void cpa_commit() {
    asm volatile("cp.async.commit_group;\n" ::: "memory");
}
template <int N>
__device__ __forceinline__ void cpa_wait() {
    asm volatile("cp.async.wait_group %0;\n" :: "n"(N) : "memory");
}

// ---------------------------------------------------------------------------
// Fused Q/K/V projection (one launch): Y = X @ W^T + bias, tf32-rounded.
//  mode 0 (Q): [bh][s][hd] plain
//  mode 1 (K): per (bh,s) a 32-float2 block; value at hd goes to
//              o = (hd>>4)*8 + (hd&3)*2 + ((hd>>3)&1), float = o*2 + ((hd>>2)&1)
//  mode 2 (V): per (bh, stile=s>>6, hd) a 32-float2 block; with sl = s&63:
//              o = (sl>>4)*8 + (sl&3)*2 + ((sl>>3)&1), float = o*2 + ((sl>>2)&1)
// ---------------------------------------------------------------------------
#define PSTG 4608   // 128*36 floats per stage per matrix

__global__ __launch_bounds__(256, 2) void proj_qkv(
    const float* __restrict__ Xq, const float* __restrict__ Wq, const float* __restrict__ bq,
    const float* __restrict__ Xk, const float* __restrict__ Wk, const float* __restrict__ bk,
    const float* __restrict__ Xv, const float* __restrict__ Wv, const float* __restrict__ bv,
    float* __restrict__ Yq, float* __restrict__ Yk, float* __restrict__ Yv)
{
    extern __shared__ float psm[];
    float* Xs = psm;
    float* Ws = psm + 2 * PSTG;

    const float *X, *W, *bias;
    float* Y;
    int mode, bxt, N_seq;
    if (blockIdx.x < 16)       { X = Xq; W = Wq; bias = bq; Y = Yq; mode = 0; bxt = blockIdx.x;      N_seq = NQ_; }
    else if (blockIdx.x < 144) { X = Xk; W = Wk; bias = bk; Y = Yk; mode = 1; bxt = blockIdx.x - 16; N_seq = NK_; }
    else                       { X = Xv; W = Wv; bias = bv; Y = Yv; mode = 2; bxt = blockIdx.x - 144; N_seq = NK_; }

    const int tid  = threadIdx.x;
    const int lane = tid & 31;
    const int w    = tid >> 5;
    const int wm   = w >> 2;
    const int wn   = w & 3;
    const int g    = lane >> 2;
    const int t    = lane & 3;
    const int bm   = bxt * 128;
    const int bn   = blockIdx.y * 128;

    unsigned xs_u = (unsigned)__cvta_generic_to_shared(Xs);
    unsigned ws_u = (unsigned)__cvta_generic_to_shared(Ws);

    float acc[4][4][4];
#pragma unroll
    for (int mi = 0; mi < 4; mi++)
#pragma unroll
        for (int nj = 0; nj < 4; nj++)
#pragma unroll
            for (int rr = 0; rr < 4; rr++) acc[mi][nj][rr] = 0.0f;

#pragma unroll
    for (int it = 0; it < 4; it++) {
        int i = it * 256 + tid;
        int r = i >> 3, c = (i & 7) * 4;
        cpa16(xs_u + (r * 36 + c) * 4, X + (size_t)(bm + r) * D_ + c);
        cpa16(ws_u + (r * 36 + c) * 4, W + (size_t)(bn + r) * D_ + c);
    }
    cpa_commit();

    for (int ki = 0; ki < 16; ki++) {
        cpa_wait<0>();
        __syncthreads();
        if (ki < 15) {
            int st = ((ki + 1) & 1) * PSTG;
            int k0 = (ki + 1) * 32;
#pragma unroll
            for (int it = 0; it < 4; it++) {
                int i = it * 256 + tid;
                int r = i >> 3, c = (i & 7) * 4;
                cpa16(xs_u + (st + r * 36 + c) * 4,
                      X + (size_t)(bm + r) * D_ + k0 + c);
                cpa16(ws_u + (st + r * 36 + c) * 4,
                      W + (size_t)(bn + r) * D_ + k0 + c);
            }
            cpa_commit();
        }
        const float* Xc = Xs + (ki & 1) * PSTG;
        const float* Wc = Ws + (ki & 1) * PSTG;

#pragma unroll
        for (int k8 = 0; k8 < 4; k8++) {
            unsigned a[4][4], b[4][2];
            int kk = k8 * 8 + t;
#pragma unroll
            for (int mi = 0; mi < 4; mi++) {
                int r = wm * 64 + mi * 16 + g;
                a[mi][0] = f2tf32(Xc[r * 36 + kk]);
                a[mi][1] = f2tf32(Xc[(r + 8) * 36 + kk]);
                a[mi][2] = f2tf32(Xc[r * 36 + kk + 4]);
                a[mi][3] = f2tf32(Xc[(r + 8) * 36 + kk + 4]);
            }
#pragma unroll
            for (int nj = 0; nj < 4; nj++) {
                int n = wn * 32 + nj * 8 + g;
                b[nj][0] = f2tf32(Wc[n * 36 + kk]);
                b[nj][1] = f2tf32(Wc[n * 36 + kk + 4]);
            }
#pragma unroll
            for (int mi = 0; mi < 4; mi++)
#pragma unroll
                for (int nj = 0; nj < 4; nj++)
                    mma_tf32(acc[mi][nj], a[mi], b[nj]);
        }
    }

#pragma unroll
    for (int mi = 0; mi < 4; mi++) {
#pragma unroll
        for (int nj = 0; nj < 4; nj++) {
            int n = bn + wn * 32 + nj * 8 + t * 2;
            float b0 = bias[n], b1 = bias[n + 1];
#pragma unroll
            for (int rr = 0; rr < 2; rr++) {
                int m = bm + wm * 64 + mi * 16 + g + rr * 8;
                float v0 = __uint_as_float(f2tf32(acc[mi][nj][rr * 2] + b0));
                float v1 = __uint_as_float(f2tf32(acc[mi][nj][rr * 2 + 1] + b1));
                int s  = m & (N_seq - 1);
                int bb = m / N_seq;
                int h  = n >> 6;
                int hd = n & 63;          // even
                int bh = bb * H_ + h;
                if (mode == 0) {
                    *reinterpret_cast<float2*>(
                        &Y[(((size_t)bh * NQ_ + s) << 6) + hd]) = make_float2(v0, v1);
                } else if (mode == 1) {
                    size_t base2 = (((size_t)bh * NK_ + s)) * 32;   // float2 units
                    int o  = ((hd >> 4) << 3) + (hd & 3) * 2 + ((hd >> 3) & 1);
                    int hf = (hd >> 2) & 1;
                    Y[(base2 + o) * 2 + hf]     = v0;   // hd
                    Y[(base2 + o + 2) * 2 + hf] = v1;   // hd+1
                } else {
                    int sl = s & 63;
                    int o  = ((sl >> 4) << 3) + (sl & 3) * 2 + ((sl >> 3) & 1);
                    int hf = (sl >> 2) & 1;
                    size_t base2 = (((size_t)bh * (NK_ / 64) + (s >> 6)) * 64 + hd) * 32;
                    Y[(base2 + o) * 2 + hf]      = v0;  // (s, hd)
                    Y[(base2 + 32 + o) * 2 + hf] = v1;  // (s, hd+1)
                }
            }
        }
    }
}

// ---------------------------------------------------------------------------
// Output projection (plain fp32 epilogue), cp.async 2-stage.
// ---------------------------------------------------------------------------
__global__ __launch_bounds__(256, 2) void proj_out(
    const float* __restrict__ X, const float* __restrict__ W,
    const float* __restrict__ bias, float* __restrict__ Y)
{
    extern __shared__ float psm[];
    float* Xs = psm;
    float* Ws = psm + 2 * PSTG;

    const int tid  = threadIdx.x;
    const int lane = tid & 31;
    const int w    = tid >> 5;
    const int wm   = w >> 2;
    const int wn   = w & 3;
    const int g    = lane >> 2;
    const int t    = lane & 3;
    const int bm   = blockIdx.x * 128;
    const int bn   = blockIdx.y * 128;

    unsigned xs_u = (unsigned)__cvta_generic_to_shared(Xs);
    unsigned ws_u = (unsigned)__cvta_generic_to_shared(Ws);

    float acc[4][4][4];
#pragma unroll
    for (int mi = 0; mi < 4; mi++)
#pragma unroll
        for (int nj = 0; nj < 4; nj++)
#pragma unroll
            for (int rr = 0; rr < 4; rr++) acc[mi][nj][rr] = 0.0f;

#pragma unroll
    for (int it = 0; it < 4; it++) {
        int i = it * 256 + tid;
        int r = i >> 3, c = (i & 7) * 4;
        cpa16(xs_u + (r * 36 + c) * 4, X + (size_t)(bm + r) * D_ + c);
        cpa16(ws_u + (r * 36 + c) * 4, W + (size_t)(bn + r) * D_ + c);
    }
    cpa_commit();

    for (int ki = 0; ki < 16; ki++) {
        cpa_wait<0>();
        __syncthreads();
        if (ki < 15) {
            int st = ((ki + 1) & 1) * PSTG;
            int k0 = (ki + 1) * 32;
#pragma unroll
            for (int it = 0; it < 4; it++) {
                int i = it * 256 + tid;
                int r = i >> 3, c = (i & 7) * 4;
                cpa16(xs_u + (st + r * 36 + c) * 4,
                      X + (size_t)(bm + r) * D_ + k0 + c);
                cpa16(ws_u + (st + r * 36 + c) * 4,
                      W + (size_t)(bn + r) * D_ + k0 + c);
            }
            cpa_commit();
        }
        const float* Xc = Xs + (ki & 1) * PSTG;
        const float* Wc = Ws + (ki & 1) * PSTG;

#pragma unroll
        for (int k8 = 0; k8 < 4; k8++) {
            unsigned a[4][4], b[4][2];
            int kk = k8 * 8 + t;
#pragma unroll
            for (int mi = 0; mi < 4; mi++) {
                int r = wm * 64 + mi * 16 + g;
                a[mi][0] = f2tf32(Xc[r * 36 + kk]);
                a[mi][1] = f2tf32(Xc[(r + 8) * 36 + kk]);
                a[mi][2] = f2tf32(Xc[r * 36 + kk + 4]);
                a[mi][3] = f2tf32(Xc[(r + 8) * 36 + kk + 4]);
            }
#pragma unroll
            for (int nj = 0; nj < 4; nj++) {
                int n = wn * 32 + nj * 8 + g;
                b[nj][0] = f2tf32(Wc[n * 36 + kk]);
                b[nj][1] = f2tf32(Wc[n * 36 + kk + 4]);
            }
#pragma unroll
            for (int mi = 0; mi < 4; mi++)
#pragma unroll
                for (int nj = 0; nj < 4; nj++)
                    mma_tf32(acc[mi][nj], a[mi], b[nj]);
        }
    }

#pragma unroll
    for (int mi = 0; mi < 4; mi++) {
#pragma unroll
        for (int nj = 0; nj < 4; nj++) {
            int n = bn + wn * 32 + nj * 8 + t * 2;
            float b0 = bias[n], b1 = bias[n + 1];
#pragma unroll
            for (int rr = 0; rr < 2; rr++) {
                int m = bm + wm * 64 + mi * 16 + g + rr * 8;
                *reinterpret_cast<float2*>(&Y[(size_t)m * D_ + n]) =
                    make_float2(acc[mi][nj][rr * 2] + b0,
                                acc[mi][nj][rr * 2 + 1] + b1);
            }
        }
    }
}

// ---------------------------------------------------------------------------
// Two-phase TF32 fused attention, LDS.128 fragment loads (k8-pair packing,
// XOR-swizzled smem). CTA = (bh, qt): 64 q rows, 4 warps.
// ---------------------------------------------------------------------------
#define KBUFB 16384            // 64 rows * 32 f2 * 8B
#define VBUFB 16384
#define ATT_SMEM_BYTES (2 * KBUFB + 2 * VBUFB)   // 65536

__global__ __launch_bounds__(128, 3) void attn_tc(
    const float* __restrict__ gQ, const float* __restrict__ gK,
    const float* __restrict__ gV, float* __restrict__ A_out,
    float* __restrict__ gctx)
{
    extern __shared__ char smc[];
    char* Kb = smc;                  // [2][KBUFB]
    char* Vb = smc + 2 * KBUFB;      // [2][VBUFB]

    const int tid  = threadIdx.x;
    const int lane = tid & 31;
    const int w    = tid >> 5;
    const int g    = lane >> 2;
    const int t    = lane & 3;
    const int bh   = blockIdx.x >> 3;
    const int qt   = blockIdx.x & 7;
    const int rw   = w * 16;
    const int sw   = (g & 1) << 2;   // frag-row swizzle (row parity = g parity)

    const float*  Qg  = gQ + ((size_t)bh * NQ_ + qt * 64 + rw) * HD_;
    const float2* Kg2 = (const float2*)gK + (size_t)bh * NK_ * 32;
    const float2* Vg2 = (const float2*)gV + (size_t)bh * NK_ * 32;
    float* Ab = A_out + ((size_t)bh * NQ_ + qt * 64) * NK_;

    unsigned kb_u = (unsigned)__cvta_generic_to_shared(Kb);
    unsigned vb_u = (unsigned)__cvta_generic_to_shared(Vb);

    // Q fragments from gmem (tf32 bits), reused for all tiles
    unsigned qa[8][4];
#pragma unroll
    for (int k8 = 0; k8 < 8; k8++) {
        int kk = k8 * 8 + t;
        qa[k8][0] = __float_as_uint(Qg[(size_t)g * HD_ + kk]);
        qa[k8][1] = __float_as_uint(Qg[(size_t)(g + 8) * HD_ + kk]);
        qa[k8][2] = __float_as_uint(Qg[(size_t)g * HD_ + kk + 4]);
        qa[k8][3] = __float_as_uint(Qg[(size_t)(g + 8) * HD_ + kk + 4]);
    }

    // cp.async copy of one 64x32-f2 tile (1024 16B chunks), swizzled dst
    const int cr = tid >> 4;             // base row 0..7
    const int cc = tid & 15;             // chunk 0..15

    // ================= PHASE 1: row sums (K only) =================
#pragma unroll
    for (int it = 0; it < 8; it++) {
        int r = it * 8 + cr;
        cpa16(kb_u + (r * 16 + (cc ^ ((r & 1) << 2))) * 16,
              Kg2 + (size_t)r * 32 + cc * 2);
    }
    cpa_commit();

    float psum0 = 0.0f, psum1 = 0.0f;

    for (int kt = 0; kt < 64; kt++) {
        cpa_wait<0>();
        __syncthreads();
        if (kt < 63) {
            const float2* Kn = Kg2 + (size_t)(kt + 1) * 64 * 32;
            unsigned kdst = kb_u + ((kt + 1) & 1) * KBUFB;
#pragma unroll
            for (int it = 0; it < 8; it++) {
                int r = it * 8 + cr;
                cpa16(kdst + (r * 16 + (cc ^ ((r & 1) << 2))) * 16,
                      Kn + (size_t)r * 32 + cc * 2);
            }
            cpa_commit();
        }
        const char* Ksm = Kb + (kt & 1) * KBUFB;

        float s[8][4];
#pragma unroll
        for (int nj = 0; nj < 8; nj++)
#pragma unroll
            for (int rr = 0; rr < 4; rr++) s[nj][rr] = 0.0f;

#pragma unroll
        for (int p = 0; p < 4; p++) {
#pragma unroll
            for (int nj = 0; nj < 8; nj++) {
                int unit = (nj * 8 + g) * 16 + ((p * 4 + t) ^ sw);
                float4 u = *reinterpret_cast<const float4*>(Ksm + unit * 16);
                mma_tf32_u(s[nj], qa[2 * p],
                           __float_as_uint(u.x), __float_as_uint(u.y));
                mma_tf32_u(s[nj], qa[2 * p + 1],
                           __float_as_uint(u.z), __float_as_uint(u.w));
            }
        }

#pragma unroll
        for (int nj = 0; nj < 8; nj++) {
            psum0 += exp2f(s[nj][0] * EXPC) + exp2f(s[nj][1] * EXPC);
            psum1 += exp2f(s[nj][2] * EXPC) + exp2f(s[nj][3] * EXPC);
        }
    }

    psum0 += __shfl_xor_sync(0xffffffffu, psum0, 1);
    psum0 += __shfl_xor_sync(0xffffffffu, psum0, 2);
    psum1 += __shfl_xor_sync(0xffffffffu, psum1, 1);
    psum1 += __shfl_xor_sync(0xffffffffu, psum1, 2);
    const float li0 = 1.0f / psum0;
    const float li1 = 1.0f / psum1;

    // ================= PHASE 2: A + ctx =================
#pragma unroll
    for (int it = 0; it < 8; it++) {
        int r = it * 8 + cr;
        unsigned doff = (r * 16 + (cc ^ ((r & 1) << 2))) * 16;
        cpa16(kb_u + doff, Kg2 + (size_t)r * 32 + cc * 2);
        cpa16(vb_u + doff, Vg2 + (size_t)r * 32 + cc * 2);
    }
    cpa_commit();

    float ctx[8][4];
#pragma unroll
    for (int nj = 0; nj < 8; nj++)
#pragma unroll
        for (int rr = 0; rr < 4; rr++) ctx[nj][rr] = 0.0f;

    const int srcA = (lane & ~3) | (t >> 1);
    const int srcB = srcA + 2;
    const bool sel = (t & 1);

    for (int kt = 0; kt < 64; kt++) {
        cpa_wait<0>();
        __syncthreads();
        if (kt < 63) {
            const float2* Kn = Kg2 + (size_t)(kt + 1) * 64 * 32;
            const float2* Vn = Vg2 + (size_t)(kt + 1) * 64 * 32;
            unsigned kdst = kb_u + ((kt + 1) & 1) * KBUFB;
            unsigned vdst = vb_u + ((kt + 1) & 1) * VBUFB;
#pragma unroll
            for (int it = 0; it < 8; it++) {
                int r = it * 8 + cr;
                unsigned doff = (r * 16 + (cc ^ ((r & 1) << 2))) * 16;
                cpa16(kdst + doff, Kn + (size_t)r * 32 + cc * 2);
                cpa16(vdst + doff, Vn + (size_t)r * 32 + cc * 2);
            }
            cpa_commit();
        }
        const char* Ksm = Kb + (kt & 1) * KBUFB;
        const char* Vsm = Vb + (kt & 1) * VBUFB;

        // ---- S = Q K^T ----
        float s[8][4];
#pragma unroll
        for (int nj = 0; nj < 8; nj++)
#pragma unroll
            for (int rr = 0; rr < 4; rr++) s[nj][rr] = 0.0f;

#pragma unroll
        for (int p = 0; p < 4; p++) {
#pragma unroll
            for (int nj = 0; nj < 8; nj++) {
                int unit = (nj * 8 + g) * 16 + ((p * 4 + t) ^ sw);
                float4 u = *reinterpret_cast<const float4*>(Ksm + unit * 16);
                mma_tf32_u(s[nj], qa[2 * p],
                           __float_as_uint(u.x), __float_as_uint(u.y));
                mma_tf32_u(s[nj], qa[2 * p + 1],
                           __float_as_uint(u.z), __float_as_uint(u.w));
            }
        }

        // ---- normalized P: write A once, keep tf32 bits for PV ----
        unsigned u0[8], u1[8], u2[8], u3[8];
#pragma unroll
        for (int nj = 0; nj < 8; nj++) {
            float p0 = exp2f(s[nj][0] * EXPC) * li0;
            float p1 = exp2f(s[nj][1] * EXPC) * li0;
            float p2 = exp2f(s[nj][2] * EXPC) * li1;
            float p3 = exp2f(s[nj][3] * EXPC) * li1;
            int col = kt * 64 + nj * 8 + t * 2;
            *reinterpret_cast<float2*>(
                &Ab[(size_t)(rw + g) * NK_ + col]) = make_float2(p0, p1);
            *reinterpret_cast<float2*>(
                &Ab[(size_t)(rw + g + 8) * NK_ + col]) = make_float2(p2, p3);
            u0[nj] = f2tf32(p0);
            u1[nj] = f2tf32(p1);
            u2[nj] = f2tf32(p2);
            u3[nj] = f2tf32(p3);
        }

        // ---- ctx += P V : A-frags via shfl, V-frags via LDS.128 (c-pairs) ----
#pragma unroll
        for (int p = 0; p < 4; p++) {
            unsigned paE[4], paO[4];
#pragma unroll
            for (int e = 0; e < 2; e++) {
                int c = 2 * p + e;
                unsigned x0 = __shfl_sync(0xffffffffu, u0[c], srcA);
                unsigned x1 = __shfl_sync(0xffffffffu, u1[c], srcA);
                unsigned y0 = __shfl_sync(0xffffffffu, u0[c], srcB);
                unsigned y1 = __shfl_sync(0xffffffffu, u1[c], srcB);
                unsigned z0 = __shfl_sync(0xffffffffu, u2[c], srcA);
                unsigned z1 = __shfl_sync(0xffffffffu, u3[c], srcA);
                unsigned w0 = __shfl_sync(0xffffffffu, u2[c], srcB);
                unsigned w1 = __shfl_sync(0xffffffffu, u3[c], srcB);
                unsigned* pa = e ? paO : paE;
                pa[0] = sel ? x1 : x0;
                pa[1] = sel ? z1 : z0;
                pa[2] = sel ? y1 : y0;
                pa[3] = sel ? w1 : w0;
            }
#pragma unroll
            for (int nj = 0; nj < 8; nj++) {
                int unit = (nj * 8 + g) * 16 + ((p * 4 + t) ^ sw);
                float4 u = *reinterpret_cast<const float4*>(Vsm + unit * 16);
                mma_tf32_u(ctx[nj], paE,
                           __float_as_uint(u.x), __float_as_uint(u.y));
                mma_tf32_u(ctx[nj], paO,
                           __float_as_uint(u.z), __float_as_uint(u.w));
            }
        }
    }

    // ---- write ctx (already normalized) ----
    const int b0 = bh >> 3;
    const int h  = bh & 7;
#pragma unroll
    for (int nj = 0; nj < 8; nj++) {
        int hd = nj * 8 + t * 2;
#pragma unroll
        for (int rr = 0; rr < 2; rr++) {
            int q = qt * 64 + rw + g + rr * 8;
            float2 v = make_float2(ctx[nj][rr * 2], ctx[nj][rr * 2 + 1]);
            *reinterpret_cast<float2*>(
                &gctx[((size_t)b0 * NQ_ + q) * D_ + h * 64 + hd]) = v;
        }
    }
}

// ---------------------------------------------------------------------------
extern "C" void kernel_launch(void* const* d_in, const int* in_sizes, int n_in,
                              void* d_out, int out_size)
{
    const float* q  = (const float*)d_in[0];
    const float* k  = (const float*)d_in[1];
    const float* v  = (const float*)d_in[2];
    const float* Wq = (const float*)d_in[3];
    const float* bq = (const float*)d_in[4];
    const float* Wk = (const float*)d_in[5];
    const float* bk = (const float*)d_in[6];
    const float* Wv = (const float*)d_in[7];
    const float* bv = (const float*)d_in[8];
    const float* Wo = (const float*)d_in[9];
    const float* bo = (const float*)d_in[10];

    float* out = (float*)d_out;                         // [B, NQ, D]
    float* A   = out + (size_t)B_ * NQ_ * D_;           // [B, H, NQ, NK]

    float *gQ, *gK, *gV, *gctx;
    cudaGetSymbolAddress((void**)&gQ,  g_Q);
    cudaGetSymbolAddress((void**)&gK,  g_K);
    cudaGetSymbolAddress((void**)&gV,  g_V);
    cudaGetSymbolAddress((void**)&gctx, g_ctx);

    const int proj_smem = 4 * PSTG * 4;   // 73728 B
    cudaFuncSetAttribute(proj_qkv,
        cudaFuncAttributeMaxDynamicSharedMemorySize, proj_smem);
    cudaFuncSetAttribute(proj_out,
        cudaFuncAttributeMaxDynamicSharedMemorySize, proj_smem);
    cudaFuncSetAttribute(attn_tc,
        cudaFuncAttributeMaxDynamicSharedMemorySize, ATT_SMEM_BYTES);

    proj_qkv<<<dim3(272, 4), 256, proj_smem>>>(
        q, Wq, bq, k, Wk, bk, v, Wv, bv, gQ, gK, gV);
    attn_tc<<<256, 128, ATT_SMEM_BYTES>>>(gQ, gK, gV, A, gctx);
    proj_out<<<dim3(16, 4), 256, proj_smem>>>(gctx, Wo, bo, out);
}

// round 13
// speedup vs baseline: 1.5718x; 1.0147x over previous
#include <cuda_runtime.h>
#include <math.h>

#define B_  4
#define H_  8
#define D_  512
#define HD_ 64
#define NQ_ 512
#define NK_ 4096

// exp(s/8) == exp2(s * 0.125 * log2(e))
#define EXPC 0.18033688011112042f

// ---------------- scratch (no-alloc rule) ----------------
__device__ float g_Q[(size_t)B_ * H_ * NQ_ * HD_];    // [bh][s][hd] tf32 bits
__device__ float g_K[(size_t)B_ * H_ * NK_ * HD_];    // k8-pair packed (attn)
__device__ float g_V[(size_t)B_ * H_ * NK_ * HD_];    // c-pair packed (attn)
__device__ float g_ctx[(size_t)B_ * NQ_ * D_];
// prepacked tf32 operands for proj_qkv
__device__ float g_Xq[(size_t)B_ * NQ_ * D_];
__device__ float g_Xk[(size_t)B_ * NK_ * D_];
__device__ float g_Xv[(size_t)B_ * NK_ * D_];
__device__ float g_Wq[(size_t)D_ * D_];
__device__ float g_Wk[(size_t)D_ * D_];
__device__ float g_Wv[(size_t)D_ * D_];

// ---------------- helpers ----------------
__device__ __forceinline__ unsigned f2tf32(float x) {
    unsigned r;
    asm("cvt.rna.tf32.f32 %0, %1;" : "=r"(r) : "f"(x));
    return r;
}

__device__ __forceinline__ void mma_tf32(float* d, const unsigned* a,
                                         const unsigned* b) {
    asm volatile(
        "mma.sync.aligned.m16n8k8.row.col.f32.tf32.tf32.f32 "
        "{%0,%1,%2,%3}, {%4,%5,%6,%7}, {%8,%9}, {%0,%1,%2,%3};"
        : "+f"(d[0]), "+f"(d[1]), "+f"(d[2]), "+f"(d[3])
        : "r"(a[0]), "r"(a[1]), "r"(a[2]), "r"(a[3]),
          "r"(b[0]), "r"(b[1]));
}

__device__ __forceinline__ void mma_tf32_u(float* d, const unsigned* a,
                                           unsigned b0, unsigned b1) {
    asm volatile(
        "mma.sync.aligned.m16n8k8.row.col.f32.tf32.tf32.f32 "
        "{%0,%1,%2,%3}, {%4,%5,%6,%7}, {%8,%9}, {%0,%1,%2,%3};"
        : "+f"(d[0]), "+f"(d[1]), "+f"(d[2]), "+f"(d[3])
        : "r"(a[0]), "r"(a[1]), "r"(a[2]), "r"(a[3]),
          "r"(b0), "r"(b1));
}

__device__ __forceinline__ void mma_tf32_f4(float* d, const float4& ra,
                                            const float4& rb, float b0, float b1) {
    // a = {ra.x, rb.x, ra.y, rb.y} (rows R, R+8 x cols t, t+4)
    asm volatile(
        "mma.sync.aligned.m16n8k8.row.col.f32.tf32.tf32.f32 "
        "{%0,%1,%2,%3}, {%4,%5,%6,%7}, {%8,%9}, {%0,%1,%2,%3};"
        : "+f"(d[0]), "+f"(d[1]), "+f"(d[2]), "+f"(d[3])
        : "r"(__float_as_uint(ra.x)), "r"(__float_as_uint(rb.x)),
          "r"(__float_as_uint(ra.y)), "r"(__float_as_uint(rb.y)),
          "r"(__float_as_uint(b0)), "r"(__float_as_uint(b1)));
}

__device__ __forceinline__ void cpa16(unsigned dst, const void* src) {
    asm volatile("cp.async.cg.shared.global [%0], [%1], 16;\n"
                 :: "r"(dst), "l"(src));
}
__device__ __forceinline__ void cpa_commit() {
    asm volatile("cp.async.commit_group;\n" ::: "memory");
}
template <int N>
__device__ __forceinline__ void cpa_wait() {
    asm volatile("cp.async.wait_group %0;\n" :: "n"(N) : "memory");
}

// ---------------------------------------------------------------------------
// Prepack: tf32-convert + fragment-pair pack X and W operands.
// Per 32-k block of each row: dest float4 chunk u (0..7) holds source
// k = ki*32 + 16*p + t + {0,4,8,12}, p = (u>>2) ^ (row&1), t = u&3.
// ---------------------------------------------------------------------------
__global__ __launch_bounds__(256) void prepack(
    const float* __restrict__ q, const float* __restrict__ k,
    const float* __restrict__ v, const float* __restrict__ Wq,
    const float* __restrict__ Wk, const float* __restrict__ Wv,
    float* __restrict__ Xq, float* __restrict__ Xk, float* __restrict__ Xv,
    float* __restrict__ Pq, float* __restrict__ Pk, float* __restrict__ Pv)
{
    int ci  = blockIdx.x * 256 + threadIdx.x;
    int row = ci >> 7;               // global row over 6 concatenated tensors
    int cr  = ci & 127;              // chunk within row (16 ki x 8 chunks)

    const float* src; float* dst; int lrow;
    if (row < 2048)       { src = q;  dst = Xq; lrow = row; }
    else if (row < 18432) { src = k;  dst = Xk; lrow = row - 2048; }
    else if (row < 34816) { src = v;  dst = Xv; lrow = row - 18432; }
    else if (row < 35328) { src = Wq; dst = Pq; lrow = row - 34816; }
    else if (row < 35840) { src = Wk; dst = Pk; lrow = row - 35328; }
    else                  { src = Wv; dst = Pv; lrow = row - 35840; }

    int ki = cr >> 3, u = cr & 7;
    int t = u & 3;
    int p = (u >> 2) ^ (lrow & 1);
    const float* s = src + (size_t)lrow * D_ + ki * 32 + p * 16 + t;
    float4 o;
    o.x = __uint_as_float(f2tf32(s[0]));
    o.y = __uint_as_float(f2tf32(s[4]));
    o.z = __uint_as_float(f2tf32(s[8]));
    o.w = __uint_as_float(f2tf32(s[12]));
    *reinterpret_cast<float4*>(dst + (size_t)lrow * D_ + ki * 32 + u * 4) = o;
}

// ---------------------------------------------------------------------------
// Fused Q/K/V projection from PREPACKED operands: Y = X @ W^T + bias.
// Fragments via LDS.128; no cvt in the loop. Epilogue layouts unchanged:
//  mode 0 (Q): [bh][s][hd] plain tf32
//  mode 1 (K): attn k8-pair packing  o = (hd>>4)*8 + (hd&3)*2 + ((hd>>3)&1)
//  mode 2 (V): attn c-pair packing over kv
// ---------------------------------------------------------------------------
#define PKSTG 4096   // 128 rows * 32 floats per stage per matrix

__global__ __launch_bounds__(256, 2) void proj_qkv(
    const float* __restrict__ Xq, const float* __restrict__ Pq, const float* __restrict__ bq,
    const float* __restrict__ Xk, const float* __restrict__ Pk, const float* __restrict__ bk,
    const float* __restrict__ Xv, const float* __restrict__ Pv, const float* __restrict__ bv,
    float* __restrict__ Yq, float* __restrict__ Yk, float* __restrict__ Yv)
{
    extern __shared__ float psm[];
    float* Xs = psm;                 // [2][PKSTG]
    float* Ws = psm + 2 * PKSTG;

    const float *X, *W, *bias;
    float* Y;
    int mode, bxt, N_seq;
    if (blockIdx.x < 16)       { X = Xq; W = Pq; bias = bq; Y = Yq; mode = 0; bxt = blockIdx.x;      N_seq = NQ_; }
    else if (blockIdx.x < 144) { X = Xk; W = Pk; bias = bk; Y = Yk; mode = 1; bxt = blockIdx.x - 16; N_seq = NK_; }
    else                       { X = Xv; W = Pv; bias = bv; Y = Yv; mode = 2; bxt = blockIdx.x - 144; N_seq = NK_; }

    const int tid  = threadIdx.x;
    const int lane = tid & 31;
    const int w    = tid >> 5;
    const int wm   = w >> 2;
    const int wn   = w & 3;
    const int g    = lane >> 2;
    const int t    = lane & 3;
    const int bm   = bxt * 128;
    const int bn   = blockIdx.y * 128;
    const int swz  = (g & 1) << 2;

    unsigned xs_u = (unsigned)__cvta_generic_to_shared(Xs);
    unsigned ws_u = (unsigned)__cvta_generic_to_shared(Ws);

    float acc[4][4][4];
#pragma unroll
    for (int mi = 0; mi < 4; mi++)
#pragma unroll
        for (int nj = 0; nj < 4; nj++)
#pragma unroll
            for (int rr = 0; rr < 4; rr++) acc[mi][nj][rr] = 0.0f;

    // prefetch stage 0 (identity copy: packed gmem layout == smem layout)
#pragma unroll
    for (int it = 0; it < 4; it++) {
        int i = it * 256 + tid;
        int r = i >> 3, c = (i & 7) * 4;
        cpa16(xs_u + (r * 32 + c) * 4, X + (size_t)(bm + r) * D_ + c);
        cpa16(ws_u + (r * 32 + c) * 4, W + (size_t)(bn + r) * D_ + c);
    }
    cpa_commit();

    for (int ki = 0; ki < 16; ki++) {
        cpa_wait<0>();
        __syncthreads();
        if (ki < 15) {
            int st = ((ki + 1) & 1) * PKSTG;
            int k0 = (ki + 1) * 32;
#pragma unroll
            for (int it = 0; it < 4; it++) {
                int i = it * 256 + tid;
                int r = i >> 3, c = (i & 7) * 4;
                cpa16(xs_u + (st + r * 32 + c) * 4,
                      X + (size_t)(bm + r) * D_ + k0 + c);
                cpa16(ws_u + (st + r * 32 + c) * 4,
                      W + (size_t)(bn + r) * D_ + k0 + c);
            }
            cpa_commit();
        }
        const float4* Xc = reinterpret_cast<const float4*>(Xs + (ki & 1) * PKSTG);
        const float4* Wc = reinterpret_cast<const float4*>(Ws + (ki & 1) * PKSTG);

#pragma unroll
        for (int p = 0; p < 2; p++) {
            int up = ((p << 2) + t) ^ swz;     // swizzled 16B unit
            float4 ua[4], ub[4], vb[4];
#pragma unroll
            for (int mi = 0; mi < 4; mi++) {
                int r = wm * 64 + mi * 16 + g;
                ua[mi] = Xc[r * 8 + up];
                ub[mi] = Xc[(r + 8) * 8 + up];
            }
#pragma unroll
            for (int nj = 0; nj < 4; nj++) {
                int n = wn * 32 + nj * 8 + g;
                vb[nj] = Wc[n * 8 + up];
            }
#pragma unroll
            for (int mi = 0; mi < 4; mi++)
#pragma unroll
                for (int nj = 0; nj < 4; nj++) {
                    mma_tf32_f4(acc[mi][nj], ua[mi], ub[mi], vb[nj].x, vb[nj].y);
                    // second k8 of the pair: components z,w
                    float4 ta = make_float4(ua[mi].z, ua[mi].w, 0.f, 0.f);
                    float4 tb = make_float4(ub[mi].z, ub[mi].w, 0.f, 0.f);
                    mma_tf32_f4(acc[mi][nj], ta, tb, vb[nj].z, vb[nj].w);
                }
        }
    }

#pragma unroll
    for (int mi = 0; mi < 4; mi++) {
#pragma unroll
        for (int nj = 0; nj < 4; nj++) {
            int n = bn + wn * 32 + nj * 8 + t * 2;
            float b0 = bias[n], b1 = bias[n + 1];
#pragma unroll
            for (int rr = 0; rr < 2; rr++) {
                int m = bm + wm * 64 + mi * 16 + g + rr * 8;
                float v0 = __uint_as_float(f2tf32(acc[mi][nj][rr * 2] + b0));
                float v1 = __uint_as_float(f2tf32(acc[mi][nj][rr * 2 + 1] + b1));
                int s  = m & (N_seq - 1);
                int bb = m / N_seq;
                int h  = n >> 6;
                int hd = n & 63;          // even
                int bh = bb * H_ + h;
                if (mode == 0) {
                    *reinterpret_cast<float2*>(
                        &Y[(((size_t)bh * NQ_ + s) << 6) + hd]) = make_float2(v0, v1);
                } else if (mode == 1) {
                    size_t base2 = (((size_t)bh * NK_ + s)) * 32;   // float2 units
                    int o  = ((hd >> 4) << 3) + (hd & 3) * 2 + ((hd >> 3) & 1);
                    int hf = (hd >> 2) & 1;
                    Y[(base2 + o) * 2 + hf]     = v0;   // hd
                    Y[(base2 + o + 2) * 2 + hf] = v1;   // hd+1
                } else {
                    int sl = s & 63;
                    int o  = ((sl >> 4) << 3) + (sl & 3) * 2 + ((sl >> 3) & 1);
                    int hf = (sl >> 2) & 1;
                    size_t base2 = (((size_t)bh * (NK_ / 64) + (s >> 6)) * 64 + hd) * 32;
                    Y[(base2 + o) * 2 + hf]      = v0;  // (s, hd)
                    Y[(base2 + 32 + o) * 2 + hf] = v1;  // (s, hd+1)
                }
            }
        }
    }
}

// ---------------------------------------------------------------------------
// Output projection (unchanged old path): cp.async raw + in-loop cvt.
// ---------------------------------------------------------------------------
#define PSTG 4608   // 128*36 floats per stage per matrix

__global__ __launch_bounds__(256, 2) void proj_out(
    const float* __restrict__ X, const float* __restrict__ W,
    const float* __restrict__ bias, float* __restrict__ Y)
{
    extern __shared__ float psm[];
    float* Xs = psm;
    float* Ws = psm + 2 * PSTG;

    const int tid  = threadIdx.x;
    const int lane = tid & 31;
    const int w    = tid >> 5;
    const int wm   = w >> 2;
    const int wn   = w & 3;
    const int g    = lane >> 2;
    const int t    = lane & 3;
    const int bm   = blockIdx.x * 128;
    const int bn   = blockIdx.y * 128;

    unsigned xs_u = (unsigned)__cvta_generic_to_shared(Xs);
    unsigned ws_u = (unsigned)__cvta_generic_to_shared(Ws);

    float acc[4][4][4];
#pragma unroll
    for (int mi = 0; mi < 4; mi++)
#pragma unroll
        for (int nj = 0; nj < 4; nj++)
#pragma unroll
            for (int rr = 0; rr < 4; rr++) acc[mi][nj][rr] = 0.0f;

#pragma unroll
    for (int it = 0; it < 4; it++) {
        int i = it * 256 + tid;
        int r = i >> 3, c = (i & 7) * 4;
        cpa16(xs_u + (r * 36 + c) * 4, X + (size_t)(bm + r) * D_ + c);
        cpa16(ws_u + (r * 36 + c) * 4, W + (size_t)(bn + r) * D_ + c);
    }
    cpa_commit();

    for (int ki = 0; ki < 16; ki++) {
        cpa_wait<0>();
        __syncthreads();
        if (ki < 15) {
            int st = ((ki + 1) & 1) * PSTG;
            int k0 = (ki + 1) * 32;
#pragma unroll
            for (int it = 0; it < 4; it++) {
                int i = it * 256 + tid;
                int r = i >> 3, c = (i & 7) * 4;
                cpa16(xs_u + (st + r * 36 + c) * 4,
                      X + (size_t)(bm + r) * D_ + k0 + c);
                cpa16(ws_u + (st + r * 36 + c) * 4,
                      W + (size_t)(bn + r) * D_ + k0 + c);
            }
            cpa_commit();
        }
        const float* Xc = Xs + (ki & 1) * PSTG;
        const float* Wc = Ws + (ki & 1) * PSTG;

#pragma unroll
        for (int k8 = 0; k8 < 4; k8++) {
            unsigned a[4][4], b[4][2];
            int kk = k8 * 8 + t;
#pragma unroll
            for (int mi = 0; mi < 4; mi++) {
                int r = wm * 64 + mi * 16 + g;
                a[mi][0] = f2tf32(Xc[r * 36 + kk]);
                a[mi][1] = f2tf32(Xc[(r + 8) * 36 + kk]);
                a[mi][2] = f2tf32(Xc[r * 36 + kk + 4]);
                a[mi][3] = f2tf32(Xc[(r + 8) * 36 + kk + 4]);
            }
#pragma unroll
            for (int nj = 0; nj < 4; nj++) {
                int n = wn * 32 + nj * 8 + g;
                b[nj][0] = f2tf32(Wc[n * 36 + kk]);
                b[nj][1] = f2tf32(Wc[n * 36 + kk + 4]);
            }
#pragma unroll
            for (int mi = 0; mi < 4; mi++)
#pragma unroll
                for (int nj = 0; nj < 4; nj++)
                    mma_tf32(acc[mi][nj], a[mi], b[nj]);
        }
    }

#pragma unroll
    for (int mi = 0; mi < 4; mi++) {
#pragma unroll
        for (int nj = 0; nj < 4; nj++) {
            int n = bn + wn * 32 + nj * 8 + t * 2;
            float b0 = bias[n], b1 = bias[n + 1];
#pragma unroll
            for (int rr = 0; rr < 2; rr++) {
                int m = bm + wm * 64 + mi * 16 + g + rr * 8;
                *reinterpret_cast<float2*>(&Y[(size_t)m * D_ + n]) =
                    make_float2(acc[mi][nj][rr * 2] + b0,
                                acc[mi][nj][rr * 2 + 1] + b1);
            }
        }
    }
}

// ---------------------------------------------------------------------------
// Two-phase TF32 fused attention (unchanged from R9).
// ---------------------------------------------------------------------------
#define KBUFB 16384            // 64 rows * 32 f2 * 8B
#define VBUFB 16384
#define ATT_SMEM_BYTES (2 * KBUFB + 2 * VBUFB)   // 65536

__global__ __launch_bounds__(128, 3) void attn_tc(
    const float* __restrict__ gQ, const float* __restrict__ gK,
    const float* __restrict__ gV, float* __restrict__ A_out,
    float* __restrict__ gctx)
{
    extern __shared__ char smc[];
    char* Kb = smc;                  // [2][KBUFB]
    char* Vb = smc + 2 * KBUFB;      // [2][VBUFB]

    const int tid  = threadIdx.x;
    const int lane = tid & 31;
    const int w    = tid >> 5;
    const int g    = lane >> 2;
    const int t    = lane & 3;
    const int bh   = blockIdx.x >> 3;
    const int qt   = blockIdx.x & 7;
    const int rw   = w * 16;
    const int sw   = (g & 1) << 2;

    const float*  Qg  = gQ + ((size_t)bh * NQ_ + qt * 64 + rw) * HD_;
    const float2* Kg2 = (const float2*)gK + (size_t)bh * NK_ * 32;
    const float2* Vg2 = (const float2*)gV + (size_t)bh * NK_ * 32;
    float* Ab = A_out + ((size_t)bh * NQ_ + qt * 64) * NK_;

    unsigned kb_u = (unsigned)__cvta_generic_to_shared(Kb);
    unsigned vb_u = (unsigned)__cvta_generic_to_shared(Vb);

    unsigned qa[8][4];
#pragma unroll
    for (int k8 = 0; k8 < 8; k8++) {
        int kk = k8 * 8 + t;
        qa[k8][0] = __float_as_uint(Qg[(size_t)g * HD_ + kk]);
        qa[k8][1] = __float_as_uint(Qg[(size_t)(g + 8) * HD_ + kk]);
        qa[k8][2] = __float_as_uint(Qg[(size_t)g * HD_ + kk + 4]);
        qa[k8][3] = __float_as_uint(Qg[(size_t)(g + 8) * HD_ + kk + 4]);
    }

    const int cr = tid >> 4;
    const int cc = tid & 15;

    // ================= PHASE 1: row sums (K only) =================
#pragma unroll
    for (int it = 0; it < 8; it++) {
        int r = it * 8 + cr;
        cpa16(kb_u + (r * 16 + (cc ^ ((r & 1) << 2))) * 16,
              Kg2 + (size_t)r * 32 + cc * 2);
    }
    cpa_commit();

    float psum0 = 0.0f, psum1 = 0.0f;

    for (int kt = 0; kt < 64; kt++) {
        cpa_wait<0>();
        __syncthreads();
        if (kt < 63) {
            const float2* Kn = Kg2 + (size_t)(kt + 1) * 64 * 32;
            unsigned kdst = kb_u + ((kt + 1) & 1) * KBUFB;
#pragma unroll
            for (int it = 0; it < 8; it++) {
                int r = it * 8 + cr;
                cpa16(kdst + (r * 16 + (cc ^ ((r & 1) << 2))) * 16,
                      Kn + (size_t)r * 32 + cc * 2);
            }
            cpa_commit();
        }
        const char* Ksm = Kb + (kt & 1) * KBUFB;

        float s[8][4];
#pragma unroll
        for (int nj = 0; nj < 8; nj++)
#pragma unroll
            for (int rr = 0; rr < 4; rr++) s[nj][rr] = 0.0f;

#pragma unroll
        for (int p = 0; p < 4; p++) {
#pragma unroll
            for (int nj = 0; nj < 8; nj++) {
                int unit = (nj * 8 + g) * 16 + ((p * 4 + t) ^ sw);
                float4 u = *reinterpret_cast<const float4*>(Ksm + unit * 16);
                mma_tf32_u(s[nj], qa[2 * p],
                           __float_as_uint(u.x), __float_as_uint(u.y));
                mma_tf32_u(s[nj], qa[2 * p + 1],
                           __float_as_uint(u.z), __float_as_uint(u.w));
            }
        }

#pragma unroll
        for (int nj = 0; nj < 8; nj++) {
            psum0 += exp2f(s[nj][0] * EXPC) + exp2f(s[nj][1] * EXPC);
            psum1 += exp2f(s[nj][2] * EXPC) + exp2f(s[nj][3] * EXPC);
        }
    }

    psum0 += __shfl_xor_sync(0xffffffffu, psum0, 1);
    psum0 += __shfl_xor_sync(0xffffffffu, psum0, 2);
    psum1 += __shfl_xor_sync(0xffffffffu, psum1, 1);
    psum1 += __shfl_xor_sync(0xffffffffu, psum1, 2);
    const float li0 = 1.0f / psum0;
    const float li1 = 1.0f / psum1;

    // ================= PHASE 2: A + ctx =================
#pragma unroll
    for (int it = 0; it < 8; it++) {
        int r = it * 8 + cr;
        unsigned doff = (r * 16 + (cc ^ ((r & 1) << 2))) * 16;
        cpa16(kb_u + doff, Kg2 + (size_t)r * 32 + cc * 2);
        cpa16(vb_u + doff, Vg2 + (size_t)r * 32 + cc * 2);
    }
    cpa_commit();

    float ctx[8][4];
#pragma unroll
    for (int nj = 0; nj < 8; nj++)
#pragma unroll
        for (int rr = 0; rr < 4; rr++) ctx[nj][rr] = 0.0f;

    const int srcA = (lane & ~3) | (t >> 1);
    const int srcB = srcA + 2;
    const bool sel = (t & 1);

    for (int kt = 0; kt < 64; kt++) {
        cpa_wait<0>();
        __syncthreads();
        if (kt < 63) {
            const float2* Kn = Kg2 + (size_t)(kt + 1) * 64 * 32;
            const float2* Vn = Vg2 + (size_t)(kt + 1) * 64 * 32;
            unsigned kdst = kb_u + ((kt + 1) & 1) * KBUFB;
            unsigned vdst = vb_u + ((kt + 1) & 1) * VBUFB;
#pragma unroll
            for (int it = 0; it < 8; it++) {
                int r = it * 8 + cr;
                unsigned doff = (r * 16 + (cc ^ ((r & 1) << 2))) * 16;
                cpa16(kdst + doff, Kn + (size_t)r * 32 + cc * 2);
                cpa16(vdst + doff, Vn + (size_t)r * 32 + cc * 2);
            }
            cpa_commit();
        }
        const char* Ksm = Kb + (kt & 1) * KBUFB;
        const char* Vsm = Vb + (kt & 1) * VBUFB;

        float s[8][4];
#pragma unroll
        for (int nj = 0; nj < 8; nj++)
#pragma unroll
            for (int rr = 0; rr < 4; rr++) s[nj][rr] = 0.0f;

#pragma unroll
        for (int p = 0; p < 4; p++) {
#pragma unroll
            for (int nj = 0; nj < 8; nj++) {
                int unit = (nj * 8 + g) * 16 + ((p * 4 + t) ^ sw);
                float4 u = *reinterpret_cast<const float4*>(Ksm + unit * 16);
                mma_tf32_u(s[nj], qa[2 * p],
                           __float_as_uint(u.x), __float_as_uint(u.y));
                mma_tf32_u(s[nj], qa[2 * p + 1],
                           __float_as_uint(u.z), __float_as_uint(u.w));
            }
        }

        unsigned u0[8], u1[8], u2[8], u3[8];
#pragma unroll
        for (int nj = 0; nj < 8; nj++) {
            float p0 = exp2f(s[nj][0] * EXPC) * li0;
            float p1 = exp2f(s[nj][1] * EXPC) * li0;
            float p2 = exp2f(s[nj][2] * EXPC) * li1;
            float p3 = exp2f(s[nj][3] * EXPC) * li1;
            int col = kt * 64 + nj * 8 + t * 2;
            *reinterpret_cast<float2*>(
                &Ab[(size_t)(rw + g) * NK_ + col]) = make_float2(p0, p1);
            *reinterpret_cast<float2*>(
                &Ab[(size_t)(rw + g + 8) * NK_ + col]) = make_float2(p2, p3);
            u0[nj] = f2tf32(p0);
            u1[nj] = f2tf32(p1);
            u2[nj] = f2tf32(p2);
            u3[nj] = f2tf32(p3);
        }

#pragma unroll
        for (int p = 0; p < 4; p++) {
            unsigned paE[4], paO[4];
#pragma unroll
            for (int e = 0; e < 2; e++) {
                int c = 2 * p + e;
                unsigned x0 = __shfl_sync(0xffffffffu, u0[c], srcA);
                unsigned x1 = __shfl_sync(0xffffffffu, u1[c], srcA);
                unsigned y0 = __shfl_sync(0xffffffffu, u0[c], srcB);
                unsigned y1 = __shfl_sync(0xffffffffu, u1[c], srcB);
                unsigned z0 = __shfl_sync(0xffffffffu, u2[c], srcA);
                unsigned z1 = __shfl_sync(0xffffffffu, u3[c], srcA);
                unsigned w0 = __shfl_sync(0xffffffffu, u2[c], srcB);
                unsigned w1 = __shfl_sync(0xffffffffu, u3[c], srcB);
                unsigned* pa = e ? paO : paE;
                pa[0] = sel ? x1 : x0;
                pa[1] = sel ? z1 : z0;
                pa[2] = sel ? y1 : y0;
                pa[3] = sel ? w1 : w0;
            }
#pragma unroll
            for (int nj = 0; nj < 8; nj++) {
                int unit = (nj * 8 + g) * 16 + ((p * 4 + t) ^ sw);
                float4 u = *reinterpret_cast<const float4*>(Vsm + unit * 16);
                mma_tf32_u(ctx[nj], paE,
                           __float_as_uint(u.x), __float_as_uint(u.y));
                mma_tf32_u(ctx[nj], paO,
                           __float_as_uint(u.z), __float_as_uint(u.w));
            }
        }
    }

    const int b0 = bh >> 3;
    const int h  = bh & 7;
#pragma unroll
    for (int nj = 0; nj < 8; nj++) {
        int hd = nj * 8 + t * 2;
#pragma unroll
        for (int rr = 0; rr < 2; rr++) {
            int q = qt * 64 + rw + g + rr * 8;
            float2 v = make_float2(ctx[nj][rr * 2], ctx[nj][rr * 2 + 1]);
            *reinterpret_cast<float2*>(
                &gctx[((size_t)b0 * NQ_ + q) * D_ + h * 64 + hd]) = v;
        }
    }
}

// ---------------------------------------------------------------------------
extern "C" void kernel_launch(void* const* d_in, const int* in_sizes, int n_in,
                              void* d_out, int out_size)
{
    const float* q  = (const float*)d_in[0];
    const float* k  = (const float*)d_in[1];
    const float* v  = (const float*)d_in[2];
    const float* Wq = (const float*)d_in[3];
    const float* bq = (const float*)d_in[4];
    const float* Wk = (const float*)d_in[5];
    const float* bk = (const float*)d_in[6];
    const float* Wv = (const float*)d_in[7];
    const float* bv = (const float*)d_in[8];
    const float* Wo = (const float*)d_in[9];
    const float* bo = (const float*)d_in[10];

    float* out = (float*)d_out;                         // [B, NQ, D]
    float* A   = out + (size_t)B_ * NQ_ * D_;           // [B, H, NQ, NK]

    float *gQ, *gK, *gV, *gctx, *gXq, *gXk, *gXv, *gWq, *gWk, *gWv;
    cudaGetSymbolAddress((void**)&gQ,  g_Q);
    cudaGetSymbolAddress((void**)&gK,  g_K);
    cudaGetSymbolAddress((void**)&gV,  g_V);
    cudaGetSymbolAddress((void**)&gctx, g_ctx);
    cudaGetSymbolAddress((void**)&gXq, g_Xq);
    cudaGetSymbolAddress((void**)&gXk, g_Xk);
    cudaGetSymbolAddress((void**)&gXv, g_Xv);
    cudaGetSymbolAddress((void**)&gWq, g_Wq);
    cudaGetSymbolAddress((void**)&gWk, g_Wk);
    cudaGetSymbolAddress((void**)&gWv, g_Wv);

    const int pk_smem = 4 * PKSTG * 4;    // 65536 B
    const int po_smem = 4 * PSTG * 4;     // 73728 B
    cudaFuncSetAttribute(proj_qkv,
        cudaFuncAttributeMaxDynamicSharedMemorySize, pk_smem);
    cudaFuncSetAttribute(proj_out,
        cudaFuncAttributeMaxDynamicSharedMemorySize, po_smem);
    cudaFuncSetAttribute(attn_tc,
        cudaFuncAttributeMaxDynamicSharedMemorySize, ATT_SMEM_BYTES);

    // 36352 rows * 128 chunks / 256 threads = 18176 blocks
    prepack<<<18176, 256>>>(q, k, v, Wq, Wk, Wv,
                            gXq, gXk, gXv, gWq, gWk, gWv);
    proj_qkv<<<dim3(272, 4), 256, pk_smem>>>(
        gXq, gWq, bq, gXk, gWk, bk, gXv, gWv, bv, gQ, gK, gV);
    attn_tc<<<256, 128, ATT_SMEM_BYTES>>>(gQ, gK, gV, A, gctx);
    proj_out<<<dim3(16, 4), 256, po_smem>>>(gctx, Wo, bo, out);
}